// round 1
// baseline (speedup 1.0000x reference)
#include <cuda_runtime.h>
#include <cuda_bf16.h>
#include <math.h>

// Problem constants
#define BATCH 16
#define CCH   2048
#define HWD   1024
#define DD    256
#define BN_RS 0.9999950000374997f   // 1/sqrt(1 + 1e-5)

// ---------------- scratch (device globals; no allocation) ----------------
__device__ float d_Yv  [BATCH * DD  * CCH];   // [B,D,C]  psi(v2l)
__device__ float d_Zl  [BATCH * CCH * DD ];   // [B,C,D]  psi(l2v) transposed
__device__ float d_adjE[BATCH * DD  * HWD];   // even channels of v2l_adj
__device__ float d_adjO[BATCH * DD  * HWD];   // odd  channels of v2l_adj
__device__ float d_lat [BATCH * DD  * HWD];   // latent
__device__ float d_lat2[BATCH * DD  * HWD];   // aff @ latent
__device__ float d_G   [BATCH * DD  * DD ];   // gram -> aff (in place)
__device__ float d_invr[BATCH * DD];          // 1/max(||latent row||,1e-12)

// ---------------- block reductions ----------------
__device__ __forceinline__ float warpSum(float v) {
    #pragma unroll
    for (int o = 16; o; o >>= 1) v += __shfl_xor_sync(0xffffffffu, v, o);
    return v;
}
__device__ __forceinline__ float warpMax(float v) {
    #pragma unroll
    for (int o = 16; o; o >>= 1) v = fmaxf(v, __shfl_xor_sync(0xffffffffu, v, o));
    return v;
}
__device__ __forceinline__ float blockSum(float v) {
    __shared__ float sh[32];
    int w = threadIdx.x >> 5, l = threadIdx.x & 31;
    v = warpSum(v);
    if (l == 0) sh[w] = v;
    __syncthreads();
    int nw = blockDim.x >> 5;
    if (w == 0) {
        float x = (l < nw) ? sh[l] : 0.0f;
        x = warpSum(x);
        if (l == 0) sh[0] = x;
    }
    __syncthreads();
    float r = sh[0];
    __syncthreads();
    return r;
}
__device__ __forceinline__ float blockMax(float v) {
    __shared__ float sh[32];
    int w = threadIdx.x >> 5, l = threadIdx.x & 31;
    v = warpMax(v);
    if (l == 0) sh[w] = v;
    __syncthreads();
    int nw = blockDim.x >> 5;
    if (w == 0) {
        float x = (l < nw) ? sh[l] : -INFINITY;
        x = warpMax(x);
        if (l == 0) sh[0] = x;
    }
    __syncthreads();
    float r = sh[0];
    __syncthreads();
    return r;
}

// ---------------- generic batched SGEMM ----------------
// Computes C[m,n] = sum_p sum_k A_p[m,k] * B_p[n or k ...]:
//   !BKM : B given as Bt rows (K-contiguous): term = A[m,k]*Bt[n,k]
//    BKM : B given K-major [K,N]            : term = A[m,k]*B[k,n]
// EPI: 0 none; 1 relu(v*g[m]*BN_RS + b[m]); 2 relu(v*g[n]*BN_RS + b[n])
// All dims assumed divisible by tile sizes (true for this problem).
template<int BM, int BN, int BK, int EPI, bool BKM, int NP>
__global__ void __launch_bounds__(256)
gemm_k(const float* __restrict__ A0, const float* __restrict__ B0,
       const float* __restrict__ A1, const float* __restrict__ B1,
       float* __restrict__ Cp, int K,
       long sA, long sB, long sC,
       int lda, int ldb, int ldc,
       const float* __restrict__ gs, const float* __restrict__ bs)
{
    constexpr int TM = BM / 16, TN = BN / 16;
    constexpr int SEGM = TM / 4, SEGN = TN / 4;
    constexpr int LSA = BM + 4, LSB = BN + 4;
    constexpr int KF4 = BK / 4;
    constexpr int NF4 = BN / 4;
    constexpr int AIT = (BM * BK) / (4 * 256);
    constexpr int BIT = (BN * BK) / (4 * 256);

    __shared__ float As[BK * LSA];
    __shared__ float Bs[BK * LSB];

    const int tid = threadIdx.x;
    const int tx = tid & 15, ty = tid >> 4;
    const int bn0 = blockIdx.x * BN;
    const int bm0 = blockIdx.y * BM;
    const int b   = blockIdx.z;

    float acc[TM][TN];
    #pragma unroll
    for (int i = 0; i < TM; i++)
        #pragma unroll
        for (int j = 0; j < TN; j++) acc[i][j] = 0.0f;

    #pragma unroll
    for (int p = 0; p < NP; p++) {
        const float* Ab = (p == 0 ? A0 : A1) + (long)b * sA + (long)bm0 * lda;
        const float* Bb = (p == 0 ? B0 : B1) + (long)b * sB;

        for (int k0 = 0; k0 < K; k0 += BK) {
            // ---- load A tile (K-contiguous rows), transpose into As[k][m]
            #pragma unroll
            for (int i = 0; i < AIT; i++) {
                int f = tid + i * 256;
                int row = f / KF4;
                int kq  = (f % KF4) * 4;
                float4 v = *(const float4*)(Ab + (long)row * lda + k0 + kq);
                As[(kq + 0) * LSA + row] = v.x;
                As[(kq + 1) * LSA + row] = v.y;
                As[(kq + 2) * LSA + row] = v.z;
                As[(kq + 3) * LSA + row] = v.w;
            }
            // ---- load B tile
            if (!BKM) {
                #pragma unroll
                for (int i = 0; i < BIT; i++) {
                    int f = tid + i * 256;
                    int row = f / KF4;
                    int kq  = (f % KF4) * 4;
                    float4 v = *(const float4*)(Bb + (long)(bn0 + row) * ldb + k0 + kq);
                    Bs[(kq + 0) * LSB + row] = v.x;
                    Bs[(kq + 1) * LSB + row] = v.y;
                    Bs[(kq + 2) * LSB + row] = v.z;
                    Bs[(kq + 3) * LSB + row] = v.w;
                }
            } else {
                #pragma unroll
                for (int i = 0; i < BIT; i++) {
                    int f = tid + i * 256;
                    int kr = f / NF4;
                    int nq = (f % NF4) * 4;
                    float4 v = *(const float4*)(Bb + (long)(k0 + kr) * ldb + bn0 + nq);
                    *(float4*)&Bs[kr * LSB + nq] = v;
                }
            }
            __syncthreads();

            // ---- compute
            #pragma unroll
            for (int k = 0; k < BK; k++) {
                float a[TM], bv[TN];
                #pragma unroll
                for (int s = 0; s < SEGM; s++) {
                    float4 v = *(const float4*)&As[k * LSA + s * (BM / SEGM) + ty * 4];
                    a[s * 4 + 0] = v.x; a[s * 4 + 1] = v.y;
                    a[s * 4 + 2] = v.z; a[s * 4 + 3] = v.w;
                }
                #pragma unroll
                for (int s = 0; s < SEGN; s++) {
                    float4 v = *(const float4*)&Bs[k * LSB + s * (BN / SEGN) + tx * 4];
                    bv[s * 4 + 0] = v.x; bv[s * 4 + 1] = v.y;
                    bv[s * 4 + 2] = v.z; bv[s * 4 + 3] = v.w;
                }
                #pragma unroll
                for (int i = 0; i < TM; i++)
                    #pragma unroll
                    for (int j = 0; j < TN; j++)
                        acc[i][j] = fmaf(a[i], bv[j], acc[i][j]);
            }
            __syncthreads();
        }
    }

    // ---- epilogue
    float* Cb = Cp + (long)b * sC;
    #pragma unroll
    for (int si = 0; si < SEGM; si++) {
        #pragma unroll
        for (int ii = 0; ii < 4; ii++) {
            int m = bm0 + si * (BM / SEGM) + ty * 4 + ii;
            float sm_ = 0.0f, bm_ = 0.0f;
            if (EPI == 1) { sm_ = gs[m] * BN_RS; bm_ = bs[m]; }
            #pragma unroll
            for (int sj = 0; sj < SEGN; sj++) {
                int n0 = bn0 + sj * (BN / SEGN) + tx * 4;
                float4 o;
                float vv[4];
                #pragma unroll
                for (int jj = 0; jj < 4; jj++) {
                    float v = acc[si * 4 + ii][sj * 4 + jj];
                    if (EPI == 1) v = fmaxf(fmaf(v, sm_, bm_), 0.0f);
                    if (EPI == 2) {
                        int n = n0 + jj;
                        v = fmaxf(fmaf(v, gs[n] * BN_RS, bs[n]), 0.0f);
                    }
                    vv[jj] = v;
                }
                o.x = vv[0]; o.y = vv[1]; o.z = vv[2]; o.w = vv[3];
                *(float4*)(Cb + (long)m * ldc + n0) = o;
            }
        }
    }
}

// ---------------- normalize v2l rows (over C) + deinterleave even/odd ----
__global__ void __launch_bounds__(256)
k_norm_v2l(const float* __restrict__ Y, float* __restrict__ E, float* __restrict__ O)
{
    long row = blockIdx.x;                 // b*256 + d
    const float* y = Y + row * (long)CCH;  // 2048 elems
    int t = threadIdx.x;
    float s = 0.0f;
    #pragma unroll
    for (int i = 0; i < 8; i++) { float v = y[t + i * 256]; s += v * v; }
    s = blockSum(s);
    float inv = 1.0f / fmaxf(sqrtf(s), 1e-12f);
    float* e = E + row * (long)HWD;
    float* o = O + row * (long)HWD;
    #pragma unroll
    for (int i = 0; i < 4; i++) {
        int m = t + i * 256;
        float2 v = *(const float2*)(y + 2 * m);
        e[m] = v.x * inv;
        o[m] = v.y * inv;
    }
}

// ---------------- normalize Zl rows (length D=256), in place -------------
__global__ void __launch_bounds__(256)
k_norm_rows(float* __restrict__ Z)
{
    long row = blockIdx.x;                 // b*2048 + c
    float* z = Z + row * (long)DD;
    int t = threadIdx.x;
    float v = z[t];
    float s = blockSum(v * v);
    float inv = 1.0f / fmaxf(sqrtf(s), 1e-12f);
    z[t] = v * inv;
}

// ---------------- latent row inverse norms -------------------------------
__global__ void __launch_bounds__(256)
k_latnorm(const float* __restrict__ L, float* __restrict__ R)
{
    long row = blockIdx.x;                 // b*256 + d
    const float* p = L + row * (long)HWD;
    int t = threadIdx.x;
    float s = 0.0f;
    #pragma unroll
    for (int i = 0; i < 4; i++) { float v = p[t + i * 256]; s += v * v; }
    s = blockSum(s);
    if (t == 0) R[row] = 1.0f / fmaxf(sqrtf(s), 1e-12f);
}

// ---------------- softmax over scaled gram rows (in place) ---------------
__global__ void __launch_bounds__(256)
k_softmax(float* __restrict__ G, const float* __restrict__ R)
{
    long row = blockIdx.x;                 // b*256 + d
    long bb = row >> 8;
    int t = threadIdx.x;
    float* g = G + row * (long)DD;
    float ri = R[row];
    float re = R[(bb << 8) + t];
    float x = g[t] * ri * re;
    float mx = blockMax(x);
    float p = expf(x - mx);
    float sm = blockSum(p);
    g[t] = p / sm;
}

// ---------------- launch ----------------
extern "C" void kernel_launch(void* const* d_in, const int* in_sizes, int n_in,
                              void* d_out, int out_size)
{
    const float* v2l = (const float*)d_in[0];
    const float* l2v = (const float*)d_in[1];
    const float* wv  = (const float*)d_in[2];
    const float* gv  = (const float*)d_in[3];
    const float* bv  = (const float*)d_in[4];
    const float* wl  = (const float*)d_in[5];
    const float* gl  = (const float*)d_in[6];
    const float* bl  = (const float*)d_in[7];
    float* out = (float*)d_out;

    float *Yv, *Zl, *E, *O, *lat, *lat2, *G, *invr;
    cudaGetSymbolAddress((void**)&Yv,   d_Yv);
    cudaGetSymbolAddress((void**)&Zl,   d_Zl);
    cudaGetSymbolAddress((void**)&E,    d_adjE);
    cudaGetSymbolAddress((void**)&O,    d_adjO);
    cudaGetSymbolAddress((void**)&lat,  d_lat);
    cudaGetSymbolAddress((void**)&lat2, d_lat2);
    cudaGetSymbolAddress((void**)&G,    d_G);
    cudaGetSymbolAddress((void**)&invr, d_invr);

    const long FEAT = (long)CCH * HWD;     // 2097152 per batch
    dim3 blk(256);

    // 1) Yv[b,d,c] = relu(bn(Wv @ V_b^T))      M=256,N=2048,K=1024 (NT)
    gemm_k<128,128,16,1,false,1><<<dim3(CCH/128, DD/128, BATCH), blk>>>(
        wv, v2l, nullptr, nullptr, Yv, HWD,
        0, FEAT, (long)DD*CCH, HWD, HWD, CCH, gv, bv);

    // 2) Zl[b,c,d] = relu(bn(X_l @ Wl^T))      M=2048,N=256,K=1024 (NT)
    gemm_k<128,128,16,2,false,1><<<dim3(DD/128, CCH/128, BATCH), blk>>>(
        l2v, wl, nullptr, nullptr, Zl, HWD,
        FEAT, 0, (long)CCH*DD, HWD, HWD, DD, gl, bl);

    // 3) row-normalize Yv over C, deinterleave -> adjE/adjO
    k_norm_v2l<<<BATCH*DD, blk>>>(Yv, E, O);

    // 4) normalize Zl rows over D (in place)
    k_norm_rows<<<BATCH*CCH, blk>>>(Zl);

    // 5) latent = adjE @ Vlow^T + adjO @ Vhigh^T   M=256,N=1024,K=1024 (NT, 2 pairs)
    gemm_k<128,128,16,0,false,2><<<dim3(HWD/128, DD/128, BATCH), blk>>>(
        E, v2l, O, v2l + (long)HWD*HWD, lat, HWD,
        (long)DD*HWD, FEAT, (long)DD*HWD, HWD, HWD, HWD, nullptr, nullptr);

    // 6) latent row inverse norms
    k_latnorm<<<BATCH*DD, blk>>>(lat, invr);

    // 7) G = latent @ latent^T                  M=N=256,K=1024 (NT, 64x64 tiles)
    gemm_k<64,64,32,0,false,1><<<dim3(DD/64, DD/64, BATCH), blk>>>(
        lat, lat, nullptr, nullptr, G, HWD,
        (long)DD*HWD, (long)DD*HWD, (long)DD*DD, HWD, HWD, DD, nullptr, nullptr);

    // 8) aff = softmax(G * invr_d * invr_e) (in place)
    k_softmax<<<BATCH*DD, blk>>>(G, invr);

    // 9) lat2 = aff @ latent                    M=256,N=1024,K=256 (NN)
    gemm_k<128,128,16,0,true,1><<<dim3(HWD/128, DD/128, BATCH), blk>>>(
        G, lat, nullptr, nullptr, lat2, DD,
        (long)DD*DD, (long)DD*HWD, (long)DD*HWD, DD, HWD, HWD, nullptr, nullptr);

    // 10) visible = Zl_adj @ lat2 -> out        M=2048,N=1024,K=256 (NN)
    gemm_k<128,128,16,0,true,1><<<dim3(HWD/128, CCH/128, BATCH), blk>>>(
        Zl, lat2, nullptr, nullptr, out, DD,
        (long)CCH*DD, (long)DD*HWD, FEAT, DD, HWD, HWD, nullptr, nullptr);
}

// round 4
// speedup vs baseline: 1.8585x; 1.8585x over previous
#include <cuda_runtime.h>
#include <cuda_bf16.h>
#include <math.h>
#include <stdint.h>

#define BATCH 16
#define CCH   2048
#define HWD   1024
#define DD    256
#define BN_RS 0.9999950000374997f   // 1/sqrt(1 + 1e-5)

// ---------------- scratch (device globals; no allocation) ----------------
__device__ float d_Yv  [BATCH * DD  * CCH];   // [B,D,C]
__device__ float d_Zl  [BATCH * CCH * DD ];   // [B,C,D]
__device__ float d_E   [BATCH * DD  * HWD];
__device__ float d_O   [BATCH * DD  * HWD];
__device__ float d_lat [BATCH * DD  * HWD];   // latent [d][h]
__device__ float d_latT[BATCH * HWD * DD ];   // latent^T [h][d]
__device__ float d_l2T [BATCH * HWD * DD ];   // (aff@latent)^T [h][d]
__device__ float d_G   [BATCH * DD  * DD ];
__device__ float d_invr[BATCH * DD];

// ---------------- helpers ----------------
__device__ __forceinline__ uint32_t cvta_s(const void* p){
    return (uint32_t)__cvta_generic_to_shared(p);
}

#define LDSM4(R, addr) \
    asm volatile("ldmatrix.sync.aligned.m8n8.x4.shared.b16 {%0,%1,%2,%3}, [%4];" \
        : "=r"((R)[0]), "=r"((R)[1]), "=r"((R)[2]), "=r"((R)[3]) : "r"(addr))

#define MMA16816(d, A, b0, b1) \
    asm volatile("mma.sync.aligned.m16n8k16.row.col.f32.bf16.bf16.f32 " \
        "{%0,%1,%2,%3}, {%4,%5,%6,%7}, {%8,%9}, {%0,%1,%2,%3};" \
        : "+f"((d)[0]), "+f"((d)[1]), "+f"((d)[2]), "+f"((d)[3]) \
        : "r"((A)[0]), "r"((A)[1]), "r"((A)[2]), "r"((A)[3]), "r"(b0), "r"(b1))

// split float4 -> packed bf16x2 hi (truncated top-16) and lo (rn of exact residual)
__device__ __forceinline__ void split16(float4 v, uint2& hi, uint2& lo){
    uint32_t ux = __float_as_uint(v.x), uy = __float_as_uint(v.y);
    uint32_t uz = __float_as_uint(v.z), uw = __float_as_uint(v.w);
    hi.x = __byte_perm(ux, uy, 0x7632);
    hi.y = __byte_perm(uz, uw, 0x7632);
    float lx = v.x - __uint_as_float(ux & 0xFFFF0000u);
    float ly = v.y - __uint_as_float(uy & 0xFFFF0000u);
    float lz = v.z - __uint_as_float(uz & 0xFFFF0000u);
    float lw = v.w - __uint_as_float(uw & 0xFFFF0000u);
    __nv_bfloat162 l01 = __floats2bfloat162_rn(lx, ly);
    __nv_bfloat162 l23 = __floats2bfloat162_rn(lz, lw);
    lo.x = *(uint32_t*)&l01;
    lo.y = *(uint32_t*)&l23;
}

// ---------------- mma.sync GEMM (NT, fp32 in/out, hi/lo bf16 3-pass) -------
// D[m,n] = sum_p sum_k A_p[m,k] * B_p[n,k]
struct GArgs {
    const float *A0, *B0, *A1, *B1;
    float* C;
    const float *gs, *bs;
    long sA, sB, sC;
    int lda, ldb, ldc, K;
};

// smem: per stage: Ah(10240) Al(10240) Bh(10240) Bl(10240) = 40960; x2 stages
#define STG   40960
#define SUBT  10240
#define MMA_SMEM (2 * STG)

template<int EPI, int NP>
__global__ void __launch_bounds__(256, 1) mma_gemm(GArgs a)
{
    extern __shared__ __align__(128) char smem[];
    const int tid = threadIdx.x, w = tid >> 5, lane = tid & 31;
    const int bn0 = blockIdx.x << 7, bm0 = blockIdx.y << 7, b = blockIdx.z;
    const int KS = a.K >> 5;
    const int NS = KS * NP;
    const uint32_t sbase = cvta_s(smem);
    const int wm = w >> 2, wn = w & 3;

    float4 rA[4], rB[4];
    auto ldg = [&](int i){
        int p = (NP == 2 && i >= KS) ? 1 : 0;
        long k0 = (long)(i - p * KS) * 32;
        const float* Ap = (p ? a.A1 : a.A0) + (long)b * a.sA + (long)bm0 * a.lda + k0;
        const float* Bp = (p ? a.B1 : a.B0) + (long)b * a.sB + (long)bn0 * a.ldb + k0;
        #pragma unroll
        for (int j = 0; j < 4; j++){
            int f = tid + j * 256, row = f >> 3, cq = f & 7;
            rA[j] = *(const float4*)(Ap + (long)row * a.lda + cq * 4);
            rB[j] = *(const float4*)(Bp + (long)row * a.ldb + cq * 4);
        }
    };
    auto sts = [&](int st){
        char* base = smem + st * STG;
        #pragma unroll
        for (int j = 0; j < 4; j++){
            int f = tid + j * 256, row = f >> 3, cq = f & 7;
            uint32_t off = (uint32_t)row * 80u + (uint32_t)cq * 8u;
            uint2 hi, lo;
            split16(rA[j], hi, lo);
            *(uint2*)(base + off)            = hi;
            *(uint2*)(base + SUBT + off)     = lo;
            split16(rB[j], hi, lo);
            *(uint2*)(base + 2 * SUBT + off) = hi;
            *(uint2*)(base + 3 * SUBT + off) = lo;
        }
    };

    float acc[4][4][4];
    #pragma unroll
    for (int i = 0; i < 4; i++)
        #pragma unroll
        for (int j = 0; j < 4; j++)
            #pragma unroll
            for (int t = 0; t < 4; t++) acc[i][j][t] = 0.0f;

    // ldmatrix lane-address offsets (bytes), relative to sub-tile base
    const uint32_t aOff = (uint32_t)(wm * 64 + (lane & 15)) * 80u + (uint32_t)(lane >> 4) * 16u;
    const uint32_t bOff = (uint32_t)(wn * 32 + (lane & 7) + ((lane >> 4) & 1) * 8) * 80u
                        + (uint32_t)((lane >> 3) & 1) * 16u;

    ldg(0); sts(0);
    __syncthreads();

    for (int i = 0; i < NS; i++){
        if (i + 1 < NS) ldg(i + 1);

        const uint32_t stb = sbase + (uint32_t)(i & 1) * STG;
        #pragma unroll
        for (int ks = 0; ks < 2; ks++){
            uint32_t Afh[4][4], Afl[4][4], Bfh[2][4], Bfl[2][4];
            #pragma unroll
            for (int mi = 0; mi < 4; mi++){
                uint32_t ad = stb + aOff + (uint32_t)mi * (16 * 80) + (uint32_t)ks * 32;
                LDSM4(Afh[mi], ad);
                LDSM4(Afl[mi], ad + SUBT);
            }
            #pragma unroll
            for (int nb = 0; nb < 2; nb++){
                uint32_t bd = stb + 2 * SUBT + bOff + (uint32_t)nb * (16 * 80) + (uint32_t)ks * 32;
                LDSM4(Bfh[nb], bd);
                LDSM4(Bfl[nb], bd + SUBT);
            }
            #pragma unroll
            for (int mi = 0; mi < 4; mi++){
                #pragma unroll
                for (int ni = 0; ni < 4; ni++){
                    int nb = ni >> 1, h = (ni & 1) * 2;
                    MMA16816(acc[mi][ni], Afh[mi], Bfh[nb][h], Bfh[nb][h + 1]);
                    MMA16816(acc[mi][ni], Afh[mi], Bfl[nb][h], Bfl[nb][h + 1]);
                    MMA16816(acc[mi][ni], Afl[mi], Bfh[nb][h], Bfh[nb][h + 1]);
                }
            }
        }
        if (i + 1 < NS) sts((i + 1) & 1);
        __syncthreads();
    }

    // ---- epilogue: fp32 (+BN/ReLU), direct from register accumulators
    const int r1 = lane >> 2, cq = (lane & 3) * 2;
    float* Cb = a.C + (long)b * a.sC;
    #pragma unroll
    for (int mi = 0; mi < 4; mi++){
        int m0 = bm0 + wm * 64 + mi * 16 + r1;
        float s0 = 0.f, b0_ = 0.f, s1 = 0.f, b1_ = 0.f;
        if (EPI == 1){
            s0 = a.gs[m0] * BN_RS;     b0_ = a.bs[m0];
            s1 = a.gs[m0 + 8] * BN_RS; b1_ = a.bs[m0 + 8];
        }
        #pragma unroll
        for (int ni = 0; ni < 4; ni++){
            int n = bn0 + wn * 32 + ni * 8 + cq;
            float v0 = acc[mi][ni][0], v1 = acc[mi][ni][1];
            float v2 = acc[mi][ni][2], v3 = acc[mi][ni][3];
            if (EPI == 1){
                v0 = fmaxf(fmaf(v0, s0, b0_), 0.f); v1 = fmaxf(fmaf(v1, s0, b0_), 0.f);
                v2 = fmaxf(fmaf(v2, s1, b1_), 0.f); v3 = fmaxf(fmaf(v3, s1, b1_), 0.f);
            } else if (EPI == 2){
                float gs0 = a.gs[n] * BN_RS, bb0 = a.bs[n];
                float gs1 = a.gs[n + 1] * BN_RS, bb1 = a.bs[n + 1];
                v0 = fmaxf(fmaf(v0, gs0, bb0), 0.f); v1 = fmaxf(fmaf(v1, gs1, bb1), 0.f);
                v2 = fmaxf(fmaf(v2, gs0, bb0), 0.f); v3 = fmaxf(fmaf(v3, gs1, bb1), 0.f);
            }
            *(float2*)(Cb + (long)m0 * a.ldc + n)       = make_float2(v0, v1);
            *(float2*)(Cb + (long)(m0 + 8) * a.ldc + n) = make_float2(v2, v3);
        }
    }
}

// ---------------- block reductions ----------------
__device__ __forceinline__ float warpSum(float v){
    #pragma unroll
    for (int o = 16; o; o >>= 1) v += __shfl_xor_sync(0xffffffffu, v, o);
    return v;
}
__device__ __forceinline__ float warpMax(float v){
    #pragma unroll
    for (int o = 16; o; o >>= 1) v = fmaxf(v, __shfl_xor_sync(0xffffffffu, v, o));
    return v;
}
__device__ __forceinline__ float blockSum(float v){
    __shared__ float sh[32];
    int w = threadIdx.x >> 5, l = threadIdx.x & 31;
    v = warpSum(v);
    if (l == 0) sh[w] = v;
    __syncthreads();
    int nw = blockDim.x >> 5;
    if (w == 0){ float x = (l < nw) ? sh[l] : 0.0f; x = warpSum(x); if (l == 0) sh[0] = x; }
    __syncthreads();
    float r = sh[0];
    __syncthreads();
    return r;
}
__device__ __forceinline__ float blockMax(float v){
    __shared__ float sh[32];
    int w = threadIdx.x >> 5, l = threadIdx.x & 31;
    v = warpMax(v);
    if (l == 0) sh[w] = v;
    __syncthreads();
    int nw = blockDim.x >> 5;
    if (w == 0){ float x = (l < nw) ? sh[l] : -INFINITY; x = warpMax(x); if (l == 0) sh[0] = x; }
    __syncthreads();
    float r = sh[0];
    __syncthreads();
    return r;
}

// ---------------- elementwise kernels ----------------
__global__ void __launch_bounds__(256)
k_norm_v2l(const float* __restrict__ Y, float* __restrict__ E, float* __restrict__ O)
{
    long row = blockIdx.x;
    const float* y = Y + row * (long)CCH;
    int t = threadIdx.x;
    float s = 0.0f;
    #pragma unroll
    for (int i = 0; i < 8; i++){ float v = y[t + i * 256]; s += v * v; }
    s = blockSum(s);
    float inv = 1.0f / fmaxf(sqrtf(s), 1e-12f);
    float* e = E + row * (long)HWD;
    float* o = O + row * (long)HWD;
    #pragma unroll
    for (int i = 0; i < 4; i++){
        int m = t + i * 256;
        float2 v = *(const float2*)(y + 2 * m);
        e[m] = v.x * inv;
        o[m] = v.y * inv;
    }
}
__global__ void __launch_bounds__(256)
k_norm_rows(float* __restrict__ Z)
{
    long row = blockIdx.x;
    float* z = Z + row * (long)DD;
    int t = threadIdx.x;
    float v = z[t];
    float s = blockSum(v * v);
    float inv = 1.0f / fmaxf(sqrtf(s), 1e-12f);
    z[t] = v * inv;
}
__global__ void __launch_bounds__(256)
k_latnorm(const float* __restrict__ L, float* __restrict__ R)
{
    long row = blockIdx.x;
    const float* p = L + row * (long)HWD;
    int t = threadIdx.x;
    float s = 0.0f;
    #pragma unroll
    for (int i = 0; i < 4; i++){ float v = p[t + i * 256]; s += v * v; }
    s = blockSum(s);
    if (t == 0) R[row] = 1.0f / fmaxf(sqrtf(s), 1e-12f);
}
__global__ void __launch_bounds__(256)
k_softmax(float* __restrict__ G, const float* __restrict__ R)
{
    long row = blockIdx.x;
    long bb = row >> 8;
    int t = threadIdx.x;
    float* g = G + row * (long)DD;
    float ri = R[row];
    float re = R[(bb << 8) + t];
    float x = g[t] * ri * re;
    float mx = blockMax(x);
    float p = expf(x - mx);
    float sm = blockSum(p);
    g[t] = p / sm;
}

// ---------------- launch ----------------
extern "C" void kernel_launch(void* const* d_in, const int* in_sizes, int n_in,
                              void* d_out, int out_size)
{
    const float* v2l = (const float*)d_in[0];
    const float* l2v = (const float*)d_in[1];
    const float* wv  = (const float*)d_in[2];
    const float* gv  = (const float*)d_in[3];
    const float* bv  = (const float*)d_in[4];
    const float* wl  = (const float*)d_in[5];
    const float* gl  = (const float*)d_in[6];
    const float* bl  = (const float*)d_in[7];
    float* out = (float*)d_out;

    float *Yv, *Zl, *E, *O, *lat, *latT, *l2T, *G, *invr;
    cudaGetSymbolAddress((void**)&Yv,   d_Yv);
    cudaGetSymbolAddress((void**)&Zl,   d_Zl);
    cudaGetSymbolAddress((void**)&E,    d_E);
    cudaGetSymbolAddress((void**)&O,    d_O);
    cudaGetSymbolAddress((void**)&lat,  d_lat);
    cudaGetSymbolAddress((void**)&latT, d_latT);
    cudaGetSymbolAddress((void**)&l2T,  d_l2T);
    cudaGetSymbolAddress((void**)&G,    d_G);
    cudaGetSymbolAddress((void**)&invr, d_invr);

    cudaFuncSetAttribute(mma_gemm<0,1>, cudaFuncAttributeMaxDynamicSharedMemorySize, MMA_SMEM);
    cudaFuncSetAttribute(mma_gemm<0,2>, cudaFuncAttributeMaxDynamicSharedMemorySize, MMA_SMEM);
    cudaFuncSetAttribute(mma_gemm<1,1>, cudaFuncAttributeMaxDynamicSharedMemorySize, MMA_SMEM);
    cudaFuncSetAttribute(mma_gemm<2,1>, cudaFuncAttributeMaxDynamicSharedMemorySize, MMA_SMEM);

    const long FEAT = (long)CCH * HWD;
    dim3 blk(256);

    // 1) Yv[d,c] = relu(bn(Wv . V^T))   M=256 N=2048 K=1024
    {
        GArgs a = { wv, v2l, nullptr, nullptr, Yv, gv, bv,
                    0, FEAT, (long)DD * CCH, HWD, HWD, CCH, HWD };
        mma_gemm<1,1><<<dim3(CCH/128, DD/128, BATCH), blk, MMA_SMEM>>>(a);
    }
    // 2) Zl[c,d] = relu(bn(Xl . Wl^T))  M=2048 N=256 K=1024
    {
        GArgs a = { l2v, wl, nullptr, nullptr, Zl, gl, bl,
                    FEAT, 0, (long)CCH * DD, HWD, HWD, DD, HWD };
        mma_gemm<2,1><<<dim3(DD/128, CCH/128, BATCH), blk, MMA_SMEM>>>(a);
    }
    // 3) normalize Yv rows over C, deinterleave -> E/O
    k_norm_v2l<<<BATCH * DD, blk>>>(Yv, E, O);
    // 4) normalize Zl rows over D
    k_norm_rows<<<BATCH * CCH, blk>>>(Zl);
    // 5a) lat[d,h] = E.Vlow^T + O.Vhigh^T   M=256 N=1024 K=1024x2
    {
        GArgs a = { E, v2l, O, v2l + (long)HWD * HWD, lat, nullptr, nullptr,
                    (long)DD * HWD, FEAT, (long)DD * HWD, HWD, HWD, HWD, HWD };
        mma_gemm<0,2><<<dim3(HWD/128, DD/128, BATCH), blk, MMA_SMEM>>>(a);
    }
    // 5b) latT[h,d] = Vlow.E^T + Vhigh.O^T  M=1024 N=256 K=1024x2
    {
        GArgs a = { v2l, E, v2l + (long)HWD * HWD, O, latT, nullptr, nullptr,
                    FEAT, (long)DD * HWD, (long)HWD * DD, HWD, HWD, DD, HWD };
        mma_gemm<0,2><<<dim3(DD/128, HWD/128, BATCH), blk, MMA_SMEM>>>(a);
    }
    // 6) latent row inverse norms
    k_latnorm<<<BATCH * DD, blk>>>(lat, invr);
    // 7) G = lat . lat^T                M=256 N=256 K=1024
    {
        GArgs a = { lat, lat, nullptr, nullptr, G, nullptr, nullptr,
                    (long)DD * HWD, (long)DD * HWD, (long)DD * DD, HWD, HWD, DD, HWD };
        mma_gemm<0,1><<<dim3(DD/128, DD/128, BATCH), blk, MMA_SMEM>>>(a);
    }
    // 8) aff = softmax(G * invr_d * invr_e)
    k_softmax<<<BATCH * DD, blk>>>(G, invr);
    // 9) l2T[h,d] = latT . aff^T        M=1024 N=256 K=256
    {
        GArgs a = { latT, G, nullptr, nullptr, l2T, nullptr, nullptr,
                    (long)HWD * DD, (long)DD * DD, (long)HWD * DD, DD, DD, DD, DD };
        mma_gemm<0,1><<<dim3(DD/128, HWD/128, BATCH), blk, MMA_SMEM>>>(a);
    }
    // 10) out[c,h] = Zl . l2T^T         M=2048 N=1024 K=256
    {
        GArgs a = { Zl, l2T, nullptr, nullptr, out, nullptr, nullptr,
                    (long)CCH * DD, (long)HWD * DD, (long)CCH * HWD, DD, DD, HWD, DD };
        mma_gemm<0,1><<<dim3(HWD/128, CCH/128, BATCH), blk, MMA_SMEM>>>(a);
    }
}

// round 5
// speedup vs baseline: 2.2357x; 1.2030x over previous
#include <cuda_runtime.h>
#include <cuda_bf16.h>
#include <math.h>
#include <stdint.h>

#define BATCH 16
#define CCH   2048
#define HWD   1024
#define DD    256
#define BN_RS 0.9999950000374997f   // 1/sqrt(1 + 1e-5)

// ---------------- scratch (device globals; no allocation) ----------------
__device__ __align__(16) float d_Yv [BATCH * DD  * CCH];   // psi(v2l) fp32
__device__ __align__(16) float d_Zl [BATCH * CCH * DD ];   // psi(l2v)^T fp32
__device__ __align__(16) float d_G  [BATCH * DD  * DD ];   // gram fp32
__device__ float d_invr[BATCH * DD];

// bf16 hi/lo split operand storage
__device__ __align__(16) __nv_bfloat16 g_v2lh[BATCH*CCH*HWD], g_v2ll[BATCH*CCH*HWD];
__device__ __align__(16) __nv_bfloat16 g_l2vh[BATCH*CCH*HWD], g_l2vl[BATCH*CCH*HWD];
__device__ __align__(16) __nv_bfloat16 g_wvh[DD*HWD], g_wvl[DD*HWD];
__device__ __align__(16) __nv_bfloat16 g_wlh[DD*HWD], g_wll[DD*HWD];
__device__ __align__(16) __nv_bfloat16 g_Eh[BATCH*DD*HWD], g_El[BATCH*DD*HWD];
__device__ __align__(16) __nv_bfloat16 g_Oh[BATCH*DD*HWD], g_Ol[BATCH*DD*HWD];
__device__ __align__(16) __nv_bfloat16 g_Zh[BATCH*CCH*DD], g_Zlo[BATCH*CCH*DD];
__device__ __align__(16) __nv_bfloat16 g_lath[BATCH*DD*HWD], g_latl[BATCH*DD*HWD];
__device__ __align__(16) __nv_bfloat16 g_latTh[BATCH*HWD*DD], g_latTl[BATCH*HWD*DD];
__device__ __align__(16) __nv_bfloat16 g_Gh[BATCH*DD*DD], g_Gl[BATCH*DD*DD];
__device__ __align__(16) __nv_bfloat16 g_l2Th[BATCH*HWD*DD], g_l2Tl[BATCH*HWD*DD];

// ---------------- helpers ----------------
__device__ __forceinline__ uint32_t cvta_s(const void* p){
    return (uint32_t)__cvta_generic_to_shared(p);
}
__device__ __forceinline__ void cpa16(uint32_t d, const void* s){
    asm volatile("cp.async.cg.shared.global [%0], [%1], 16;" :: "r"(d), "l"(s));
}
#define CP_COMMIT() asm volatile("cp.async.commit_group;")
#define CP_WAIT2()  asm volatile("cp.async.wait_group 2;")

#define LDSM4(R, addr) \
    asm volatile("ldmatrix.sync.aligned.m8n8.x4.shared.b16 {%0,%1,%2,%3}, [%4];" \
        : "=r"((R)[0]), "=r"((R)[1]), "=r"((R)[2]), "=r"((R)[3]) : "r"(addr))

#define MMA16816(d, A, b0, b1) \
    asm volatile("mma.sync.aligned.m16n8k16.row.col.f32.bf16.bf16.f32 " \
        "{%0,%1,%2,%3}, {%4,%5,%6,%7}, {%8,%9}, {%0,%1,%2,%3};" \
        : "+f"((d)[0]), "+f"((d)[1]), "+f"((d)[2]), "+f"((d)[3]) \
        : "r"((A)[0]), "r"((A)[1]), "r"((A)[2]), "r"((A)[3]), "r"(b0), "r"(b1))

// split float4 -> packed bf16x2 hi (trunc) / lo (rn of exact residual)
__device__ __forceinline__ void split16(float4 v, uint2& hi, uint2& lo){
    uint32_t ux = __float_as_uint(v.x), uy = __float_as_uint(v.y);
    uint32_t uz = __float_as_uint(v.z), uw = __float_as_uint(v.w);
    hi.x = __byte_perm(ux, uy, 0x7632);
    hi.y = __byte_perm(uz, uw, 0x7632);
    float lx = v.x - __uint_as_float(ux & 0xFFFF0000u);
    float ly = v.y - __uint_as_float(uy & 0xFFFF0000u);
    float lz = v.z - __uint_as_float(uz & 0xFFFF0000u);
    float lw = v.w - __uint_as_float(uw & 0xFFFF0000u);
    __nv_bfloat162 l01 = __floats2bfloat162_rn(lx, ly);
    __nv_bfloat162 l23 = __floats2bfloat162_rn(lz, lw);
    lo.x = *(uint32_t*)&l01;
    lo.y = *(uint32_t*)&l23;
}
__device__ __forceinline__ uint32_t pack_hi(float x, float y){
    return __byte_perm(__float_as_uint(x), __float_as_uint(y), 0x7632);
}
__device__ __forceinline__ uint32_t pack_lo(float x, float y){
    float lx = x - __uint_as_float(__float_as_uint(x) & 0xFFFF0000u);
    float ly = y - __uint_as_float(__float_as_uint(y) & 0xFFFF0000u);
    __nv_bfloat162 p = __floats2bfloat162_rn(lx, ly);
    return *(uint32_t*)&p;
}

// ---------------- bf16 hi/lo NT GEMM, cp.async pipelined -------------------
// D[m,n] = sum_p sum_k A_p[m,k]*B_p[n,k], 3 bf16 passes (hh + hl + lh)
struct GArgs {
    const __nv_bfloat16 *A0h, *A0l, *B0h, *B0l;
    const __nv_bfloat16 *A1h, *A1l, *B1h, *B1l;
    void *C, *C2;                   // EPI 0/1/2: C=float*; EPI 3: C=hi bf16*, C2=lo bf16*
    const float *gs, *bs;
    long sA, sB, sC;
    int lda, ldb, ldc, K;
};

// stage: Ah(8K) Al(8K) Bh(8K) Bl(8K) = 32KB; subtile rows = 64B (32 bf16), 4x16B chunks
// swizzled quarter q = ch ^ ((row>>1)&3)
#define GSTG   32768
#define GSUB   8192
#define G_SMEM (4 * GSTG)

template<int EPI, int NP>
__global__ void __launch_bounds__(256, 1) mma_gemm(GArgs a)
{
    extern __shared__ __align__(128) char smem[];
    const int tid = threadIdx.x, w = tid >> 5, lane = tid & 31;
    const int bn0 = blockIdx.x << 7, bm0 = blockIdx.y << 7, b = blockIdx.z;
    const int KS = a.K >> 5;
    const int NS = KS * NP;
    const uint32_t sbase = cvta_s(smem);
    const int wm = w >> 2, wn = w & 3;

    // cp.async mapping: thread handles rows r0, r0+64 at chunk ch for all 4 subtiles
    const int r0 = tid >> 2, ch = tid & 3;
    const uint32_t q16 = (uint32_t)((ch ^ ((r0 >> 1) & 3)) * 16);

    auto issue = [&](int s){
        int p = (NP == 2 && s >= KS) ? 1 : 0;
        long k0 = (long)(s - p * KS) * 32;
        const __nv_bfloat16* srcs[4] = {
            (p ? a.A1h : a.A0h) + (long)b * a.sA + (long)bm0 * a.lda + k0,
            (p ? a.A1l : a.A0l) + (long)b * a.sA + (long)bm0 * a.lda + k0,
            (p ? a.B1h : a.B0h) + (long)b * a.sB + (long)bn0 * a.ldb + k0,
            (p ? a.B1l : a.B0l) + (long)b * a.sB + (long)bn0 * a.ldb + k0
        };
        uint32_t dst0 = sbase + (uint32_t)(s & 3) * GSTG + (uint32_t)r0 * 64u + q16;
        #pragma unroll
        for (int sub = 0; sub < 4; sub++){
            long ld = (sub < 2) ? a.lda : a.ldb;
            const __nv_bfloat16* sp = srcs[sub] + (long)r0 * ld + ch * 8;
            cpa16(dst0 + sub * GSUB,             sp);
            cpa16(dst0 + sub * GSUB + 64 * 64,   sp + 64 * ld);
        }
    };

    float acc[4][4][4];
    #pragma unroll
    for (int i = 0; i < 4; i++)
        #pragma unroll
        for (int j = 0; j < 4; j++)
            #pragma unroll
            for (int t = 0; t < 4; t++) acc[i][j][t] = 0.0f;

    // ldmatrix addressing
    const int aRow = wm * 64 + (lane & 15);
    const uint32_t lqA = (uint32_t)(((lane & 15) >> 1) & 3);
    const uint32_t aC0 = (uint32_t)(lane >> 4);
    const int bRow = wn * 32 + (lane & 7) + ((lane >> 4) & 1) * 8;
    const uint32_t lqB = (uint32_t)(((lane & 7) >> 1) & 3);
    const uint32_t bC0 = (uint32_t)((lane >> 3) & 1);

    // prologue: 3 stages in flight
    #pragma unroll
    for (int s = 0; s < 3; s++){ if (s < NS) issue(s); CP_COMMIT(); }

    for (int i = 0; i < NS; i++){
        CP_WAIT2();
        __syncthreads();
        const uint32_t stb = sbase + (uint32_t)(i & 3) * GSTG;
        #pragma unroll
        for (int ks = 0; ks < 2; ks++){
            uint32_t Afh[4][4], Afl[4][4], Bfh[2][4], Bfl[2][4];
            const uint32_t qa = ((aC0 + 2 * ks) ^ lqA) * 16u;
            const uint32_t qb = ((bC0 + 2 * ks) ^ lqB) * 16u;
            #pragma unroll
            for (int mi = 0; mi < 4; mi++){
                uint32_t ad = stb + (uint32_t)(aRow + mi * 16) * 64u + qa;
                LDSM4(Afh[mi], ad);
                LDSM4(Afl[mi], ad + GSUB);
            }
            #pragma unroll
            for (int nb = 0; nb < 2; nb++){
                uint32_t bd = stb + 2u * GSUB + (uint32_t)(bRow + nb * 16) * 64u + qb;
                LDSM4(Bfh[nb], bd);
                LDSM4(Bfl[nb], bd + GSUB);
            }
            // pass 1: Ah*Bh
            #pragma unroll
            for (int mi = 0; mi < 4; mi++)
                #pragma unroll
                for (int ni = 0; ni < 4; ni++){
                    int nb = ni >> 1, h = (ni & 1) * 2;
                    MMA16816(acc[mi][ni], Afh[mi], Bfh[nb][h], Bfh[nb][h + 1]);
                }
            // pass 2: Ah*Bl
            #pragma unroll
            for (int mi = 0; mi < 4; mi++)
                #pragma unroll
                for (int ni = 0; ni < 4; ni++){
                    int nb = ni >> 1, h = (ni & 1) * 2;
                    MMA16816(acc[mi][ni], Afh[mi], Bfl[nb][h], Bfl[nb][h + 1]);
                }
            // pass 3: Al*Bh
            #pragma unroll
            for (int mi = 0; mi < 4; mi++)
                #pragma unroll
                for (int ni = 0; ni < 4; ni++){
                    int nb = ni >> 1, h = (ni & 1) * 2;
                    MMA16816(acc[mi][ni], Afl[mi], Bfh[nb][h], Bfh[nb][h + 1]);
                }
        }
        if (i + 3 < NS) issue(i + 3);
        CP_COMMIT();
    }

    // ---- epilogue
    const int r1 = lane >> 2, cq = (lane & 3) * 2;
    if (EPI == 3){
        __nv_bfloat16* Ch = (__nv_bfloat16*)a.C;
        __nv_bfloat16* Cl = (__nv_bfloat16*)a.C2;
        const long cb = (long)b * a.sC;
        #pragma unroll
        for (int mi = 0; mi < 4; mi++){
            int m0 = bm0 + wm * 64 + mi * 16 + r1;
            #pragma unroll
            for (int ni = 0; ni < 4; ni++){
                int n = bn0 + wn * 32 + ni * 8 + cq;
                float v0 = acc[mi][ni][0], v1 = acc[mi][ni][1];
                float v2 = acc[mi][ni][2], v3 = acc[mi][ni][3];
                *(uint32_t*)(Ch + cb + (long)m0 * a.ldc + n)       = pack_hi(v0, v1);
                *(uint32_t*)(Cl + cb + (long)m0 * a.ldc + n)       = pack_lo(v0, v1);
                *(uint32_t*)(Ch + cb + (long)(m0 + 8) * a.ldc + n) = pack_hi(v2, v3);
                *(uint32_t*)(Cl + cb + (long)(m0 + 8) * a.ldc + n) = pack_lo(v2, v3);
            }
        }
    } else {
        float* Cb = (float*)a.C + (long)b * a.sC;
        #pragma unroll
        for (int mi = 0; mi < 4; mi++){
            int m0 = bm0 + wm * 64 + mi * 16 + r1;
            float s0 = 0.f, b0_ = 0.f, s1 = 0.f, b1_ = 0.f;
            if (EPI == 1){
                s0 = a.gs[m0] * BN_RS;     b0_ = a.bs[m0];
                s1 = a.gs[m0 + 8] * BN_RS; b1_ = a.bs[m0 + 8];
            }
            #pragma unroll
            for (int ni = 0; ni < 4; ni++){
                int n = bn0 + wn * 32 + ni * 8 + cq;
                float v0 = acc[mi][ni][0], v1 = acc[mi][ni][1];
                float v2 = acc[mi][ni][2], v3 = acc[mi][ni][3];
                if (EPI == 1){
                    v0 = fmaxf(fmaf(v0, s0, b0_), 0.f); v1 = fmaxf(fmaf(v1, s0, b0_), 0.f);
                    v2 = fmaxf(fmaf(v2, s1, b1_), 0.f); v3 = fmaxf(fmaf(v3, s1, b1_), 0.f);
                } else if (EPI == 2){
                    float gs0 = a.gs[n] * BN_RS, bb0 = a.bs[n];
                    float gs1 = a.gs[n + 1] * BN_RS, bb1 = a.bs[n + 1];
                    v0 = fmaxf(fmaf(v0, gs0, bb0), 0.f); v1 = fmaxf(fmaf(v1, gs1, bb1), 0.f);
                    v2 = fmaxf(fmaf(v2, gs0, bb0), 0.f); v3 = fmaxf(fmaf(v3, gs1, bb1), 0.f);
                }
                *(float2*)(Cb + (long)m0 * a.ldc + n)       = make_float2(v0, v1);
                *(float2*)(Cb + (long)(m0 + 8) * a.ldc + n) = make_float2(v2, v3);
            }
        }
    }
}

// ---------------- reductions ----------------
__device__ __forceinline__ float warpSum(float v){
    #pragma unroll
    for (int o = 16; o; o >>= 1) v += __shfl_xor_sync(0xffffffffu, v, o);
    return v;
}
__device__ __forceinline__ float warpMax(float v){
    #pragma unroll
    for (int o = 16; o; o >>= 1) v = fmaxf(v, __shfl_xor_sync(0xffffffffu, v, o));
    return v;
}
__device__ __forceinline__ float blockSum(float v){
    __shared__ float sh[32];
    int w = threadIdx.x >> 5, l = threadIdx.x & 31;
    v = warpSum(v);
    if (l == 0) sh[w] = v;
    __syncthreads();
    int nw = blockDim.x >> 5;
    if (w == 0){ float x = (l < nw) ? sh[l] : 0.0f; x = warpSum(x); if (l == 0) sh[0] = x; }
    __syncthreads();
    float r = sh[0];
    __syncthreads();
    return r;
}
__device__ __forceinline__ float blockMax(float v){
    __shared__ float sh[32];
    int w = threadIdx.x >> 5, l = threadIdx.x & 31;
    v = warpMax(v);
    if (l == 0) sh[w] = v;
    __syncthreads();
    int nw = blockDim.x >> 5;
    if (w == 0){ float x = (l < nw) ? sh[l] : -INFINITY; x = warpMax(x); if (l == 0) sh[0] = x; }
    __syncthreads();
    float r = sh[0];
    __syncthreads();
    return r;
}

// ---------------- elementwise kernels ----------------
__global__ void __launch_bounds__(256)
k_split(const float4* __restrict__ in, uint2* __restrict__ hi, uint2* __restrict__ lo, int n4)
{
    int i = blockIdx.x * blockDim.x + threadIdx.x;
    int stride = gridDim.x * blockDim.x;
    for (; i < n4; i += stride){
        float4 v = in[i];
        uint2 h, l;
        split16(v, h, l);
        hi[i] = h;
        lo[i] = l;
    }
}

// normalize Yv rows over C=2048, deinterleave even/odd channels, write split bf16
__global__ void __launch_bounds__(256)
k_norm_v2l(const float4* __restrict__ Y,
           uint32_t* __restrict__ Eh, uint32_t* __restrict__ El,
           uint32_t* __restrict__ Oh, uint32_t* __restrict__ Ol)
{
    long row = blockIdx.x;
    const float4* y = Y + row * 512;
    int t = threadIdx.x;
    float4 v0 = y[t], v1 = y[t + 256];
    float s = v0.x*v0.x + v0.y*v0.y + v0.z*v0.z + v0.w*v0.w
            + v1.x*v1.x + v1.y*v1.y + v1.z*v1.z + v1.w*v1.w;
    s = blockSum(s);
    float inv = 1.0f / fmaxf(sqrtf(s), 1e-12f);
    long eb = row * 512;
    // float4 at pack-index p covers channels 4p..4p+3 = e[2p],o[2p],e[2p+1],o[2p+1]
    Eh[eb + t] = pack_hi(v0.x * inv, v0.z * inv);
    El[eb + t] = pack_lo(v0.x * inv, v0.z * inv);
    Oh[eb + t] = pack_hi(v0.y * inv, v0.w * inv);
    Ol[eb + t] = pack_lo(v0.y * inv, v0.w * inv);
    Eh[eb + t + 256] = pack_hi(v1.x * inv, v1.z * inv);
    El[eb + t + 256] = pack_lo(v1.x * inv, v1.z * inv);
    Oh[eb + t + 256] = pack_hi(v1.y * inv, v1.w * inv);
    Ol[eb + t + 256] = pack_lo(v1.y * inv, v1.w * inv);
}

// normalize Zl rows over D=256, write split bf16
__global__ void __launch_bounds__(128)
k_norm_rows(const float* __restrict__ Z, uint32_t* __restrict__ Zh, uint32_t* __restrict__ Zl)
{
    long row = blockIdx.x;
    const float2* z = (const float2*)(Z + row * 256);
    int t = threadIdx.x;
    float2 v = z[t];
    float s = blockSum(v.x * v.x + v.y * v.y);
    float inv = 1.0f / fmaxf(sqrtf(s), 1e-12f);
    Zh[row * 128 + t] = pack_hi(v.x * inv, v.y * inv);
    Zl[row * 128 + t] = pack_lo(v.x * inv, v.y * inv);
}

// transpose lat_hi/lo [b,256,1024] -> latT_hi/lo [b,1024,256]  (bf16, u32-packed)
__global__ void __launch_bounds__(256)
k_transpose(const uint32_t* __restrict__ sH, const uint32_t* __restrict__ sL,
            uint32_t* __restrict__ dH, uint32_t* __restrict__ dL)
{
    __shared__ unsigned short tile[32][34];
    const int b = blockIdx.z, h0 = blockIdx.x * 32, d0 = blockIdx.y * 32;
    const int t = threadIdx.x;
    const uint32_t* srcs[2] = {sH, sL};
    uint32_t* dsts[2] = {dH, dL};
    #pragma unroll
    for (int m = 0; m < 2; m++){
        #pragma unroll
        for (int i = 0; i < 2; i++){
            int s = t + i * 256;
            int d = s >> 4, hu = s & 15;
            uint32_t v = srcs[m][(long)(b * 256 + d0 + d) * 512 + (h0 >> 1) + hu];
            tile[d][2 * hu]     = (unsigned short)(v & 0xFFFFu);
            tile[d][2 * hu + 1] = (unsigned short)(v >> 16);
        }
        __syncthreads();
        #pragma unroll
        for (int i = 0; i < 2; i++){
            int s = t + i * 256;
            int h = s >> 4, du = s & 15;
            uint32_t v = (uint32_t)tile[2 * du][h] | ((uint32_t)tile[2 * du + 1][h] << 16);
            dsts[m][(long)(b * 1024 + h0 + h) * 128 + (d0 >> 1) + du] = v;
        }
        __syncthreads();
    }
}

// latent row inverse norms from hi/lo
__global__ void __launch_bounds__(256)
k_latnorm(const uint32_t* __restrict__ H, const uint32_t* __restrict__ L, float* __restrict__ R)
{
    long row = blockIdx.x;
    long base = row * 512;
    int t = threadIdx.x;
    float s = 0.0f;
    #pragma unroll
    for (int i = 0; i < 2; i++){
        long idx = base + t + i * 256;
        uint32_t uh = H[idx], ul = L[idx];
        float2 fh = __bfloat1622float2(*(__nv_bfloat162*)&uh);
        float2 fl = __bfloat1622float2(*(__nv_bfloat162*)&ul);
        float v0 = fh.x + fl.x, v1 = fh.y + fl.y;
        s += v0 * v0 + v1 * v1;
    }
    s = blockSum(s);
    if (t == 0) R[row] = 1.0f / fmaxf(sqrtf(s), 1e-12f);
}

// softmax over scaled gram rows; write split bf16
__global__ void __launch_bounds__(256)
k_softmax(const float* __restrict__ G, const float* __restrict__ R,
          uint32_t* __restrict__ Gh, uint32_t* __restrict__ Gl)
{
    long row = blockIdx.x;
    long bb = row >> 8;
    int t = threadIdx.x;
    float ri = R[row];
    float re = R[(bb << 8) + t];
    float x = G[row * 256 + t] * ri * re;
    float mx = blockMax(x);
    float p = expf(x - mx);
    float sm = blockSum(p);
    float g = p / sm;
    float gn = __shfl_down_sync(0xffffffffu, g, 1);
    if ((t & 1) == 0){
        Gh[row * 128 + (t >> 1)] = pack_hi(g, gn);
        Gl[row * 128 + (t >> 1)] = pack_lo(g, gn);
    }
}

// ---------------- launch ----------------
extern "C" void kernel_launch(void* const* d_in, const int* in_sizes, int n_in,
                              void* d_out, int out_size)
{
    const float* v2l = (const float*)d_in[0];
    const float* l2v = (const float*)d_in[1];
    const float* wv  = (const float*)d_in[2];
    const float* gv  = (const float*)d_in[3];
    const float* bv  = (const float*)d_in[4];
    const float* wl  = (const float*)d_in[5];
    const float* gl  = (const float*)d_in[6];
    const float* bl  = (const float*)d_in[7];
    float* out = (float*)d_out;

    float *Yv, *Zl, *G, *invr;
    __nv_bfloat16 *v2lh, *v2ll, *l2vh, *l2vl, *wvh, *wvl, *wlh, *wll;
    __nv_bfloat16 *Eh, *El, *Oh, *Ol, *Zh, *Zlo, *lath, *latl, *latTh, *latTl;
    __nv_bfloat16 *Ghb, *Glb, *l2Th, *l2Tl;
    cudaGetSymbolAddress((void**)&Yv, d_Yv);
    cudaGetSymbolAddress((void**)&Zl, d_Zl);
    cudaGetSymbolAddress((void**)&G, d_G);
    cudaGetSymbolAddress((void**)&invr, d_invr);
    cudaGetSymbolAddress((void**)&v2lh, g_v2lh); cudaGetSymbolAddress((void**)&v2ll, g_v2ll);
    cudaGetSymbolAddress((void**)&l2vh, g_l2vh); cudaGetSymbolAddress((void**)&l2vl, g_l2vl);
    cudaGetSymbolAddress((void**)&wvh, g_wvh);   cudaGetSymbolAddress((void**)&wvl, g_wvl);
    cudaGetSymbolAddress((void**)&wlh, g_wlh);   cudaGetSymbolAddress((void**)&wll, g_wll);
    cudaGetSymbolAddress((void**)&Eh, g_Eh);     cudaGetSymbolAddress((void**)&El, g_El);
    cudaGetSymbolAddress((void**)&Oh, g_Oh);     cudaGetSymbolAddress((void**)&Ol, g_Ol);
    cudaGetSymbolAddress((void**)&Zh, g_Zh);     cudaGetSymbolAddress((void**)&Zlo, g_Zlo);
    cudaGetSymbolAddress((void**)&lath, g_lath); cudaGetSymbolAddress((void**)&latl, g_latl);
    cudaGetSymbolAddress((void**)&latTh, g_latTh); cudaGetSymbolAddress((void**)&latTl, g_latTl);
    cudaGetSymbolAddress((void**)&Ghb, g_Gh);    cudaGetSymbolAddress((void**)&Glb, g_Gl);
    cudaGetSymbolAddress((void**)&l2Th, g_l2Th); cudaGetSymbolAddress((void**)&l2Tl, g_l2Tl);

    cudaFuncSetAttribute(mma_gemm<0,1>, cudaFuncAttributeMaxDynamicSharedMemorySize, G_SMEM);
    cudaFuncSetAttribute(mma_gemm<1,1>, cudaFuncAttributeMaxDynamicSharedMemorySize, G_SMEM);
    cudaFuncSetAttribute(mma_gemm<2,1>, cudaFuncAttributeMaxDynamicSharedMemorySize, G_SMEM);
    cudaFuncSetAttribute(mma_gemm<3,1>, cudaFuncAttributeMaxDynamicSharedMemorySize, G_SMEM);
    cudaFuncSetAttribute(mma_gemm<3,2>, cudaFuncAttributeMaxDynamicSharedMemorySize, G_SMEM);

    const long FEAT = (long)CCH * HWD;
    dim3 blk(256);

    // 0) splits of raw inputs + weights
    k_split<<<8192, blk>>>((const float4*)v2l, (uint2*)v2lh, (uint2*)v2ll, (int)(BATCH*FEAT/4));
    k_split<<<8192, blk>>>((const float4*)l2v, (uint2*)l2vh, (uint2*)l2vl, (int)(BATCH*FEAT/4));
    k_split<<<256, blk>>>((const float4*)wv, (uint2*)wvh, (uint2*)wvl, DD*HWD/4);
    k_split<<<256, blk>>>((const float4*)wl, (uint2*)wlh, (uint2*)wll, DD*HWD/4);

    // 1) Yv = relu(bn(Wv . V^T))  M=256 N=2048 K=1024
    {
        GArgs a = { wvh, wvl, v2lh, v2ll, nullptr, nullptr, nullptr, nullptr,
                    Yv, nullptr, gv, bv, 0, FEAT, (long)DD*CCH, HWD, HWD, CCH, HWD };
        mma_gemm<1,1><<<dim3(CCH/128, DD/128, BATCH), blk, G_SMEM>>>(a);
    }
    // 2) Zl = relu(bn(Xl . Wl^T)) M=2048 N=256 K=1024
    {
        GArgs a = { l2vh, l2vl, wlh, wll, nullptr, nullptr, nullptr, nullptr,
                    Zl, nullptr, gl, bl, FEAT, 0, (long)CCH*DD, HWD, HWD, DD, HWD };
        mma_gemm<2,1><<<dim3(DD/128, CCH/128, BATCH), blk, G_SMEM>>>(a);
    }
    // 3) norm Yv rows -> split E/O
    k_norm_v2l<<<BATCH*DD, blk>>>((const float4*)Yv,
        (uint32_t*)Eh, (uint32_t*)El, (uint32_t*)Oh, (uint32_t*)Ol);
    // 4) norm Zl rows -> split Zh/Zlo
    k_norm_rows<<<BATCH*CCH, 128>>>(Zl, (uint32_t*)Zh, (uint32_t*)Zlo);
    // 5) lat = E.Vlow^T + O.Vhigh^T  M=256 N=1024 K=1024x2 -> split bf16 out
    {
        GArgs a = { Eh, El, v2lh, v2ll, Oh, Ol, v2lh + (long)HWD*HWD, v2ll + (long)HWD*HWD,
                    lath, latl, nullptr, nullptr,
                    (long)DD*HWD, FEAT, (long)DD*HWD, HWD, HWD, HWD, HWD };
        mma_gemm<3,2><<<dim3(HWD/128, DD/128, BATCH), blk, G_SMEM>>>(a);
    }
    // 6) transpose lat -> latT
    k_transpose<<<dim3(32, 8, BATCH), blk>>>(
        (const uint32_t*)lath, (const uint32_t*)latl, (uint32_t*)latTh, (uint32_t*)latTl);
    // 7) latent row inverse norms
    k_latnorm<<<BATCH*DD, blk>>>((const uint32_t*)lath, (const uint32_t*)latl, invr);
    // 8) G = lat . lat^T  M=N=256 K=1024 (fp32 out)
    {
        GArgs a = { lath, latl, lath, latl, nullptr, nullptr, nullptr, nullptr,
                    G, nullptr, nullptr, nullptr,
                    (long)DD*HWD, (long)DD*HWD, (long)DD*DD, HWD, HWD, DD, HWD };
        mma_gemm<0,1><<<dim3(DD/128, DD/128, BATCH), blk, G_SMEM>>>(a);
    }
    // 9) aff = softmax(G * invr_d * invr_e) -> split bf16
    k_softmax<<<BATCH*DD, blk>>>(G, invr, (uint32_t*)Ghb, (uint32_t*)Glb);
    // 10) l2T = latT . aff^T  M=1024 N=256 K=256 -> split bf16
    {
        GArgs a = { latTh, latTl, Ghb, Glb, nullptr, nullptr, nullptr, nullptr,
                    l2Th, l2Tl, nullptr, nullptr,
                    (long)HWD*DD, (long)DD*DD, (long)HWD*DD, DD, DD, DD, DD };
        mma_gemm<3,1><<<dim3(DD/128, HWD/128, BATCH), blk, G_SMEM>>>(a);
    }
    // 11) out = Zl_adj . l2T^T  M=2048 N=1024 K=256 (fp32 out)
    {
        GArgs a = { Zh, Zlo, l2Th, l2Tl, nullptr, nullptr, nullptr, nullptr,
                    out, nullptr, nullptr, nullptr,
                    (long)CCH*DD, (long)HWD*DD, (long)CCH*HWD, DD, DD, HWD, DD };
        mma_gemm<0,1><<<dim3(HWD/128, CCH/128, BATCH), blk, G_SMEM>>>(a);
    }
}

// round 6
// speedup vs baseline: 2.2358x; 1.0000x over previous
#include <cuda_runtime.h>
#include <cuda_bf16.h>
#include <math.h>
#include <stdint.h>

#define BATCH 16
#define CCH   2048
#define HWD   1024
#define DD    256
#define BN_RS 0.9999950000374997f   // 1/sqrt(1 + 1e-5)

// ---------------- scratch (device globals; no allocation) ----------------
__device__ __align__(16) float d_Yv [BATCH * DD  * CCH];   // psi(v2l) fp32
__device__ __align__(16) float d_Zl [BATCH * CCH * DD ];   // psi(l2v)^T fp32
__device__ __align__(16) float d_G  [BATCH * DD  * DD ];   // gram fp32
__device__ float d_invr[BATCH * DD];

// bf16 hi/lo split operand storage
__device__ __align__(16) __nv_bfloat16 g_v2lh[BATCH*CCH*HWD], g_v2ll[BATCH*CCH*HWD];
__device__ __align__(16) __nv_bfloat16 g_l2vh[BATCH*CCH*HWD], g_l2vl[BATCH*CCH*HWD];
__device__ __align__(16) __nv_bfloat16 g_wvh[DD*HWD], g_wvl[DD*HWD];
__device__ __align__(16) __nv_bfloat16 g_wlh[DD*HWD], g_wll[DD*HWD];
__device__ __align__(16) __nv_bfloat16 g_Eh[BATCH*DD*HWD], g_El[BATCH*DD*HWD];
__device__ __align__(16) __nv_bfloat16 g_Oh[BATCH*DD*HWD], g_Ol[BATCH*DD*HWD];
__device__ __align__(16) __nv_bfloat16 g_Zh[BATCH*CCH*DD], g_Zlo[BATCH*CCH*DD];
__device__ __align__(16) __nv_bfloat16 g_lath[BATCH*DD*HWD], g_latl[BATCH*DD*HWD];
__device__ __align__(16) __nv_bfloat16 g_latTh[BATCH*HWD*DD], g_latTl[BATCH*HWD*DD];
__device__ __align__(16) __nv_bfloat16 g_Gh[BATCH*DD*DD], g_Gl[BATCH*DD*DD];
__device__ __align__(16) __nv_bfloat16 g_l2Th[BATCH*HWD*DD], g_l2Tl[BATCH*HWD*DD];

// ---------------- helpers ----------------
__device__ __forceinline__ uint32_t cvta_s(const void* p){
    return (uint32_t)__cvta_generic_to_shared(p);
}
__device__ __forceinline__ void cpa16(uint32_t d, const void* s){
    asm volatile("cp.async.cg.shared.global [%0], [%1], 16;" :: "r"(d), "l"(s));
}
#define CP_COMMIT() asm volatile("cp.async.commit_group;")
#define CP_WAIT2()  asm volatile("cp.async.wait_group 2;")

#define LDSM4(R, addr) \
    asm volatile("ldmatrix.sync.aligned.m8n8.x4.shared.b16 {%0,%1,%2,%3}, [%4];" \
        : "=r"((R)[0]), "=r"((R)[1]), "=r"((R)[2]), "=r"((R)[3]) : "r"(addr))

#define MMA16816(d, A, b0, b1) \
    asm volatile("mma.sync.aligned.m16n8k16.row.col.f32.bf16.bf16.f32 " \
        "{%0,%1,%2,%3}, {%4,%5,%6,%7}, {%8,%9}, {%0,%1,%2,%3};" \
        : "+f"((d)[0]), "+f"((d)[1]), "+f"((d)[2]), "+f"((d)[3]) \
        : "r"((A)[0]), "r"((A)[1]), "r"((A)[2]), "r"((A)[3]), "r"(b0), "r"(b1))

// split float4 -> packed bf16x2 hi (trunc) / lo (rn of exact residual)
__device__ __forceinline__ void split16(float4 v, uint2& hi, uint2& lo){
    uint32_t ux = __float_as_uint(v.x), uy = __float_as_uint(v.y);
    uint32_t uz = __float_as_uint(v.z), uw = __float_as_uint(v.w);
    hi.x = __byte_perm(ux, uy, 0x7632);
    hi.y = __byte_perm(uz, uw, 0x7632);
    float lx = v.x - __uint_as_float(ux & 0xFFFF0000u);
    float ly = v.y - __uint_as_float(uy & 0xFFFF0000u);
    float lz = v.z - __uint_as_float(uz & 0xFFFF0000u);
    float lw = v.w - __uint_as_float(uw & 0xFFFF0000u);
    __nv_bfloat162 l01 = __floats2bfloat162_rn(lx, ly);
    __nv_bfloat162 l23 = __floats2bfloat162_rn(lz, lw);
    lo.x = *(uint32_t*)&l01;
    lo.y = *(uint32_t*)&l23;
}
__device__ __forceinline__ uint32_t pack_hi(float x, float y){
    return __byte_perm(__float_as_uint(x), __float_as_uint(y), 0x7632);
}
__device__ __forceinline__ uint32_t pack_lo(float x, float y){
    float lx = x - __uint_as_float(__float_as_uint(x) & 0xFFFF0000u);
    float ly = y - __uint_as_float(__float_as_uint(y) & 0xFFFF0000u);
    __nv_bfloat162 p = __floats2bfloat162_rn(lx, ly);
    return *(uint32_t*)&p;
}

// ---------------- bf16 hi/lo NT GEMM, cp.async pipelined -------------------
// D[m,n] = sum_p sum_k A_p[m,k]*B_p[n,k], 3 bf16 passes (hh + hl + lh)
struct GArgs {
    const __nv_bfloat16 *A0h, *A0l, *B0h, *B0l;
    const __nv_bfloat16 *A1h, *A1l, *B1h, *B1l;
    void *C, *C2;                   // EPI 0/1/2: C=float*; EPI 3: C=hi bf16*, C2=lo bf16*
    const float *gs, *bs;
    long sA, sB, sC;
    int lda, ldb, ldc, K;
};

// Tile: BM x 128, K-chunk 32. Stage: Ah(BM*64) Al(BM*64) Bh(8K) Bl(8K).
// Row = 64B (32 bf16), 4x16B chunks, swizzled quarter q = ch ^ ((row>>1)&3).
template<int EPI, int NP, int BM>
__global__ void __launch_bounds__(256, 1) mma_gemm(GArgs a)
{
    constexpr int WNW  = (BM == 128) ? 32 : 64;  // warp N width
    constexpr int NI   = WNW / 8;                // 4 or 8 n8-blocks per warp
    constexpr int NB   = WNW / 16;               // 2 or 4 ldmatrix B blocks
    constexpr int GSUBA = BM * 64;               // bytes per A subtile
    constexpr int GS    = 2 * GSUBA + 16384;     // stage bytes
    constexpr int BOFF  = 2 * GSUBA;             // Bh offset in stage

    extern __shared__ __align__(128) char smem[];
    const int tid = threadIdx.x, w = tid >> 5, lane = tid & 31;
    const int bn0 = blockIdx.x << 7, bm0 = blockIdx.y * BM, b = blockIdx.z;
    const int KS = a.K >> 5;
    const int NS = KS * NP;
    const uint32_t sbase = cvta_s(smem);
    const int wm = (BM == 128) ? (w >> 2) : (w >> 1);
    const int wn = (BM == 128) ? (w & 3)  : (w & 1);

    // cp.async mapping
    const int r0 = tid >> 2, ch = tid & 3;
    const uint32_t q16 = (uint32_t)((ch ^ ((r0 >> 1) & 3)) * 16);

    auto issue = [&](int s){
        int p = (NP == 2 && s >= KS) ? 1 : 0;
        long k0 = (long)(s - p * KS) * 32;
        const __nv_bfloat16* Ah = (p ? a.A1h : a.A0h) + (long)b * a.sA + (long)bm0 * a.lda + k0;
        const __nv_bfloat16* Al = (p ? a.A1l : a.A0l) + (long)b * a.sA + (long)bm0 * a.lda + k0;
        const __nv_bfloat16* Bh = (p ? a.B1h : a.B0h) + (long)b * a.sB + (long)bn0 * a.ldb + k0;
        const __nv_bfloat16* Bl = (p ? a.B1l : a.B0l) + (long)b * a.sB + (long)bn0 * a.ldb + k0;
        uint32_t dst0 = sbase + (uint32_t)(s & 3) * GS + (uint32_t)r0 * 64u + q16;
        const __nv_bfloat16* ap = Ah + (long)r0 * a.lda + ch * 8;
        const __nv_bfloat16* lp = Al + (long)r0 * a.lda + ch * 8;
        #pragma unroll
        for (int jj = 0; jj < BM / 64; jj++){
            cpa16(dst0 + jj * 4096,         ap + (long)jj * 64 * a.lda);
            cpa16(dst0 + GSUBA + jj * 4096, lp + (long)jj * 64 * a.lda);
        }
        const __nv_bfloat16* bp = Bh + (long)r0 * a.ldb + ch * 8;
        const __nv_bfloat16* blp = Bl + (long)r0 * a.ldb + ch * 8;
        #pragma unroll
        for (int jj = 0; jj < 2; jj++){
            cpa16(dst0 + BOFF + jj * 4096,        bp + (long)jj * 64 * a.ldb);
            cpa16(dst0 + BOFF + 8192 + jj * 4096, blp + (long)jj * 64 * a.ldb);
        }
    };

    float acc[4][NI][4];
    #pragma unroll
    for (int i = 0; i < 4; i++)
        #pragma unroll
        for (int j = 0; j < NI; j++)
            #pragma unroll
            for (int t = 0; t < 4; t++) acc[i][j][t] = 0.0f;

    // ldmatrix addressing
    const int aRow = wm * 64 + (lane & 15);
    const uint32_t lqA = (uint32_t)(((lane & 15) >> 1) & 3);
    const uint32_t aC0 = (uint32_t)(lane >> 4);
    const int bRow = wn * WNW + (lane & 7) + ((lane >> 4) & 1) * 8;
    const uint32_t lqB = (uint32_t)(((lane & 7) >> 1) & 3);
    const uint32_t bC0 = (uint32_t)((lane >> 3) & 1);

    // prologue: 3 stages in flight
    #pragma unroll
    for (int s = 0; s < 3; s++){ if (s < NS) issue(s); CP_COMMIT(); }

    for (int i = 0; i < NS; i++){
        CP_WAIT2();
        __syncthreads();
        if (i + 3 < NS) issue(i + 3);    // overlap DMA with the MMA block below
        CP_COMMIT();

        const uint32_t stb = sbase + (uint32_t)(i & 3) * GS;
        #pragma unroll
        for (int ks = 0; ks < 2; ks++){
            uint32_t Afh[4][4], Afl[4][4], Bfh[NB][4], Bfl[NB][4];
            const uint32_t qa = ((aC0 + 2 * ks) ^ lqA) * 16u;
            const uint32_t qb = ((bC0 + 2 * ks) ^ lqB) * 16u;
            #pragma unroll
            for (int mi = 0; mi < 4; mi++){
                uint32_t ad = stb + (uint32_t)(aRow + mi * 16) * 64u + qa;
                LDSM4(Afh[mi], ad);
                LDSM4(Afl[mi], ad + GSUBA);
            }
            #pragma unroll
            for (int nb = 0; nb < NB; nb++){
                uint32_t bd = stb + BOFF + (uint32_t)(bRow + nb * 16) * 64u + qb;
                LDSM4(Bfh[nb], bd);
                LDSM4(Bfl[nb], bd + 8192);
            }
            // pass 1: Ah*Bh
            #pragma unroll
            for (int mi = 0; mi < 4; mi++)
                #pragma unroll
                for (int ni = 0; ni < NI; ni++){
                    int nb = ni >> 1, h = (ni & 1) * 2;
                    MMA16816(acc[mi][ni], Afh[mi], Bfh[nb][h], Bfh[nb][h + 1]);
                }
            // pass 2: Ah*Bl
            #pragma unroll
            for (int mi = 0; mi < 4; mi++)
                #pragma unroll
                for (int ni = 0; ni < NI; ni++){
                    int nb = ni >> 1, h = (ni & 1) * 2;
                    MMA16816(acc[mi][ni], Afh[mi], Bfl[nb][h], Bfl[nb][h + 1]);
                }
            // pass 3: Al*Bh
            #pragma unroll
            for (int mi = 0; mi < 4; mi++)
                #pragma unroll
                for (int ni = 0; ni < NI; ni++){
                    int nb = ni >> 1, h = (ni & 1) * 2;
                    MMA16816(acc[mi][ni], Afl[mi], Bfh[nb][h], Bfh[nb][h + 1]);
                }
        }
    }

    // ---- epilogue
    const int r1 = lane >> 2, cq = (lane & 3) * 2;
    if (EPI == 3){
        __nv_bfloat16* Ch = (__nv_bfloat16*)a.C;
        __nv_bfloat16* Cl = (__nv_bfloat16*)a.C2;
        const long cb = (long)b * a.sC;
        #pragma unroll
        for (int mi = 0; mi < 4; mi++){
            int m0 = bm0 + wm * 64 + mi * 16 + r1;
            #pragma unroll
            for (int ni = 0; ni < NI; ni++){
                int n = bn0 + wn * WNW + ni * 8 + cq;
                float v0 = acc[mi][ni][0], v1 = acc[mi][ni][1];
                float v2 = acc[mi][ni][2], v3 = acc[mi][ni][3];
                *(uint32_t*)(Ch + cb + (long)m0 * a.ldc + n)       = pack_hi(v0, v1);
                *(uint32_t*)(Cl + cb + (long)m0 * a.ldc + n)       = pack_lo(v0, v1);
                *(uint32_t*)(Ch + cb + (long)(m0 + 8) * a.ldc + n) = pack_hi(v2, v3);
                *(uint32_t*)(Cl + cb + (long)(m0 + 8) * a.ldc + n) = pack_lo(v2, v3);
            }
        }
    } else {
        float* Cb = (float*)a.C + (long)b * a.sC;
        #pragma unroll
        for (int mi = 0; mi < 4; mi++){
            int m0 = bm0 + wm * 64 + mi * 16 + r1;
            float s0 = 0.f, b0_ = 0.f, s1 = 0.f, b1_ = 0.f;
            if (EPI == 1){
                s0 = a.gs[m0] * BN_RS;     b0_ = a.bs[m0];
                s1 = a.gs[m0 + 8] * BN_RS; b1_ = a.bs[m0 + 8];
            }
            #pragma unroll
            for (int ni = 0; ni < NI; ni++){
                int n = bn0 + wn * WNW + ni * 8 + cq;
                float v0 = acc[mi][ni][0], v1 = acc[mi][ni][1];
                float v2 = acc[mi][ni][2], v3 = acc[mi][ni][3];
                if (EPI == 1){
                    v0 = fmaxf(fmaf(v0, s0, b0_), 0.f); v1 = fmaxf(fmaf(v1, s0, b0_), 0.f);
                    v2 = fmaxf(fmaf(v2, s1, b1_), 0.f); v3 = fmaxf(fmaf(v3, s1, b1_), 0.f);
                } else if (EPI == 2){
                    float gs0 = a.gs[n] * BN_RS, bb0 = a.bs[n];
                    float gs1 = a.gs[n + 1] * BN_RS, bb1 = a.bs[n + 1];
                    v0 = fmaxf(fmaf(v0, gs0, bb0), 0.f); v1 = fmaxf(fmaf(v1, gs1, bb1), 0.f);
                    v2 = fmaxf(fmaf(v2, gs0, bb0), 0.f); v3 = fmaxf(fmaf(v3, gs1, bb1), 0.f);
                }
                *(float2*)(Cb + (long)m0 * a.ldc + n)       = make_float2(v0, v1);
                *(float2*)(Cb + (long)(m0 + 8) * a.ldc + n) = make_float2(v2, v3);
            }
        }
    }
}

#define SMEM_128 (4 * (2 * 128 * 64 + 16384))
#define SMEM_256 (4 * (2 * 256 * 64 + 16384))

// ---------------- reductions ----------------
__device__ __forceinline__ float warpSum(float v){
    #pragma unroll
    for (int o = 16; o; o >>= 1) v += __shfl_xor_sync(0xffffffffu, v, o);
    return v;
}
__device__ __forceinline__ float warpMax(float v){
    #pragma unroll
    for (int o = 16; o; o >>= 1) v = fmaxf(v, __shfl_xor_sync(0xffffffffu, v, o));
    return v;
}
__device__ __forceinline__ float blockSum(float v){
    __shared__ float sh[32];
    int w = threadIdx.x >> 5, l = threadIdx.x & 31;
    v = warpSum(v);
    if (l == 0) sh[w] = v;
    __syncthreads();
    int nw = blockDim.x >> 5;
    if (w == 0){ float x = (l < nw) ? sh[l] : 0.0f; x = warpSum(x); if (l == 0) sh[0] = x; }
    __syncthreads();
    float r = sh[0];
    __syncthreads();
    return r;
}
__device__ __forceinline__ float blockMax(float v){
    __shared__ float sh[32];
    int w = threadIdx.x >> 5, l = threadIdx.x & 31;
    v = warpMax(v);
    if (l == 0) sh[w] = v;
    __syncthreads();
    int nw = blockDim.x >> 5;
    if (w == 0){ float x = (l < nw) ? sh[l] : -INFINITY; x = warpMax(x); if (l == 0) sh[0] = x; }
    __syncthreads();
    float r = sh[0];
    __syncthreads();
    return r;
}

// ---------------- elementwise kernels ----------------
__global__ void __launch_bounds__(256)
k_split(const float4* __restrict__ in, uint2* __restrict__ hi, uint2* __restrict__ lo, int n4)
{
    int i = blockIdx.x * blockDim.x + threadIdx.x;
    int stride = gridDim.x * blockDim.x;
    for (; i < n4; i += stride){
        float4 v = in[i];
        uint2 h, l;
        split16(v, h, l);
        hi[i] = h;
        lo[i] = l;
    }
}

// normalize Yv rows over C=2048, deinterleave even/odd channels, write split bf16
__global__ void __launch_bounds__(256)
k_norm_v2l(const float4* __restrict__ Y,
           uint32_t* __restrict__ Eh, uint32_t* __restrict__ El,
           uint32_t* __restrict__ Oh, uint32_t* __restrict__ Ol)
{
    long row = blockIdx.x;
    const float4* y = Y + row * 512;
    int t = threadIdx.x;
    float4 v0 = y[t], v1 = y[t + 256];
    float s = v0.x*v0.x + v0.y*v0.y + v0.z*v0.z + v0.w*v0.w
            + v1.x*v1.x + v1.y*v1.y + v1.z*v1.z + v1.w*v1.w;
    s = blockSum(s);
    float inv = 1.0f / fmaxf(sqrtf(s), 1e-12f);
    long eb = row * 512;
    Eh[eb + t] = pack_hi(v0.x * inv, v0.z * inv);
    El[eb + t] = pack_lo(v0.x * inv, v0.z * inv);
    Oh[eb + t] = pack_hi(v0.y * inv, v0.w * inv);
    Ol[eb + t] = pack_lo(v0.y * inv, v0.w * inv);
    Eh[eb + t + 256] = pack_hi(v1.x * inv, v1.z * inv);
    El[eb + t + 256] = pack_lo(v1.x * inv, v1.z * inv);
    Oh[eb + t + 256] = pack_hi(v1.y * inv, v1.w * inv);
    Ol[eb + t + 256] = pack_lo(v1.y * inv, v1.w * inv);
}

// normalize Zl rows over D=256, write split bf16
__global__ void __launch_bounds__(128)
k_norm_rows(const float* __restrict__ Z, uint32_t* __restrict__ Zh, uint32_t* __restrict__ Zl)
{
    long row = blockIdx.x;
    const float2* z = (const float2*)(Z + row * 256);
    int t = threadIdx.x;
    float2 v = z[t];
    float s = blockSum(v.x * v.x + v.y * v.y);
    float inv = 1.0f / fmaxf(sqrtf(s), 1e-12f);
    Zh[row * 128 + t] = pack_hi(v.x * inv, v.y * inv);
    Zl[row * 128 + t] = pack_lo(v.x * inv, v.y * inv);
}

// transpose lat_hi/lo [b,256,1024] -> latT_hi/lo [b,1024,256]
__global__ void __launch_bounds__(256)
k_transpose(const uint32_t* __restrict__ sH, const uint32_t* __restrict__ sL,
            uint32_t* __restrict__ dH, uint32_t* __restrict__ dL)
{
    __shared__ unsigned short tile[32][34];
    const int b = blockIdx.z, h0 = blockIdx.x * 32, d0 = blockIdx.y * 32;
    const int t = threadIdx.x;
    const uint32_t* srcs[2] = {sH, sL};
    uint32_t* dsts[2] = {dH, dL};
    #pragma unroll
    for (int m = 0; m < 2; m++){
        #pragma unroll
        for (int i = 0; i < 2; i++){
            int s = t + i * 256;
            int d = s >> 4, hu = s & 15;
            uint32_t v = srcs[m][(long)(b * 256 + d0 + d) * 512 + (h0 >> 1) + hu];
            tile[d][2 * hu]     = (unsigned short)(v & 0xFFFFu);
            tile[d][2 * hu + 1] = (unsigned short)(v >> 16);
        }
        __syncthreads();
        #pragma unroll
        for (int i = 0; i < 2; i++){
            int s = t + i * 256;
            int h = s >> 4, du = s & 15;
            uint32_t v = (uint32_t)tile[2 * du][h] | ((uint32_t)tile[2 * du + 1][h] << 16);
            dsts[m][(long)(b * 1024 + h0 + h) * 128 + (d0 >> 1) + du] = v;
        }
        __syncthreads();
    }
}

// latent row inverse norms from hi/lo
__global__ void __launch_bounds__(256)
k_latnorm(const uint32_t* __restrict__ H, const uint32_t* __restrict__ L, float* __restrict__ R)
{
    long row = blockIdx.x;
    long base = row * 512;
    int t = threadIdx.x;
    float s = 0.0f;
    #pragma unroll
    for (int i = 0; i < 2; i++){
        long idx = base + t + i * 256;
        uint32_t uh = H[idx], ul = L[idx];
        float2 fh = __bfloat1622float2(*(__nv_bfloat162*)&uh);
        float2 fl = __bfloat1622float2(*(__nv_bfloat162*)&ul);
        float v0 = fh.x + fl.x, v1 = fh.y + fl.y;
        s += v0 * v0 + v1 * v1;
    }
    s = blockSum(s);
    if (t == 0) R[row] = 1.0f / fmaxf(sqrtf(s), 1e-12f);
}

// softmax over scaled gram rows; write split bf16
__global__ void __launch_bounds__(256)
k_softmax(const float* __restrict__ G, const float* __restrict__ R,
          uint32_t* __restrict__ Gh, uint32_t* __restrict__ Gl)
{
    long row = blockIdx.x;
    long bb = row >> 8;
    int t = threadIdx.x;
    float ri = R[row];
    float re = R[(bb << 8) + t];
    float x = G[row * 256 + t] * ri * re;
    float mx = blockMax(x);
    float p = expf(x - mx);
    float sm = blockSum(p);
    float g = p / sm;
    float gn = __shfl_down_sync(0xffffffffu, g, 1);
    if ((t & 1) == 0){
        Gh[row * 128 + (t >> 1)] = pack_hi(g, gn);
        Gl[row * 128 + (t >> 1)] = pack_lo(g, gn);
    }
}

// ---------------- launch ----------------
extern "C" void kernel_launch(void* const* d_in, const int* in_sizes, int n_in,
                              void* d_out, int out_size)
{
    const float* v2l = (const float*)d_in[0];
    const float* l2v = (const float*)d_in[1];
    const float* wv  = (const float*)d_in[2];
    const float* gv  = (const float*)d_in[3];
    const float* bv  = (const float*)d_in[4];
    const float* wl  = (const float*)d_in[5];
    const float* gl  = (const float*)d_in[6];
    const float* bl  = (const float*)d_in[7];
    float* out = (float*)d_out;

    float *Yv, *Zl, *G, *invr;
    __nv_bfloat16 *v2lh, *v2ll, *l2vh, *l2vl, *wvh, *wvl, *wlh, *wll;
    __nv_bfloat16 *Eh, *El, *Oh, *Ol, *Zh, *Zlo, *lath, *latl, *latTh, *latTl;
    __nv_bfloat16 *Ghb, *Glb, *l2Th, *l2Tl;
    cudaGetSymbolAddress((void**)&Yv, d_Yv);
    cudaGetSymbolAddress((void**)&Zl, d_Zl);
    cudaGetSymbolAddress((void**)&G, d_G);
    cudaGetSymbolAddress((void**)&invr, d_invr);
    cudaGetSymbolAddress((void**)&v2lh, g_v2lh); cudaGetSymbolAddress((void**)&v2ll, g_v2ll);
    cudaGetSymbolAddress((void**)&l2vh, g_l2vh); cudaGetSymbolAddress((void**)&l2vl, g_l2vl);
    cudaGetSymbolAddress((void**)&wvh, g_wvh);   cudaGetSymbolAddress((void**)&wvl, g_wvl);
    cudaGetSymbolAddress((void**)&wlh, g_wlh);   cudaGetSymbolAddress((void**)&wll, g_wll);
    cudaGetSymbolAddress((void**)&Eh, g_Eh);     cudaGetSymbolAddress((void**)&El, g_El);
    cudaGetSymbolAddress((void**)&Oh, g_Oh);     cudaGetSymbolAddress((void**)&Ol, g_Ol);
    cudaGetSymbolAddress((void**)&Zh, g_Zh);     cudaGetSymbolAddress((void**)&Zlo, g_Zlo);
    cudaGetSymbolAddress((void**)&lath, g_lath); cudaGetSymbolAddress((void**)&latl, g_latl);
    cudaGetSymbolAddress((void**)&latTh, g_latTh); cudaGetSymbolAddress((void**)&latTl, g_latTl);
    cudaGetSymbolAddress((void**)&Ghb, g_Gh);    cudaGetSymbolAddress((void**)&Glb, g_Gl);
    cudaGetSymbolAddress((void**)&l2Th, g_l2Th); cudaGetSymbolAddress((void**)&l2Tl, g_l2Tl);

    cudaFuncSetAttribute(mma_gemm<1,1,256>, cudaFuncAttributeMaxDynamicSharedMemorySize, SMEM_256);
    cudaFuncSetAttribute(mma_gemm<2,1,256>, cudaFuncAttributeMaxDynamicSharedMemorySize, SMEM_256);
    cudaFuncSetAttribute(mma_gemm<3,2,256>, cudaFuncAttributeMaxDynamicSharedMemorySize, SMEM_256);
    cudaFuncSetAttribute(mma_gemm<0,1,256>, cudaFuncAttributeMaxDynamicSharedMemorySize, SMEM_256);
    cudaFuncSetAttribute(mma_gemm<0,1,128>, cudaFuncAttributeMaxDynamicSharedMemorySize, SMEM_128);
    cudaFuncSetAttribute(mma_gemm<3,1,128>, cudaFuncAttributeMaxDynamicSharedMemorySize, SMEM_128);

    const long FEAT = (long)CCH * HWD;
    dim3 blk(256);

    // 0) splits of raw inputs + weights
    k_split<<<8192, blk>>>((const float4*)v2l, (uint2*)v2lh, (uint2*)v2ll, (int)(BATCH*FEAT/4));
    k_split<<<8192, blk>>>((const float4*)l2v, (uint2*)l2vh, (uint2*)l2vl, (int)(BATCH*FEAT/4));
    k_split<<<256, blk>>>((const float4*)wv, (uint2*)wvh, (uint2*)wvl, DD*HWD/4);
    k_split<<<256, blk>>>((const float4*)wl, (uint2*)wlh, (uint2*)wll, DD*HWD/4);

    // 1) Yv = relu(bn(Wv . V^T))  M=256 N=2048 K=1024
    {
        GArgs a = { wvh, wvl, v2lh, v2ll, nullptr, nullptr, nullptr, nullptr,
                    Yv, nullptr, gv, bv, 0, FEAT, (long)DD*CCH, HWD, HWD, CCH, HWD };
        mma_gemm<1,1,256><<<dim3(CCH/128, DD/256, BATCH), blk, SMEM_256>>>(a);
    }
    // 2) Zl = relu(bn(Xl . Wl^T)) M=2048 N=256 K=1024
    {
        GArgs a = { l2vh, l2vl, wlh, wll, nullptr, nullptr, nullptr, nullptr,
                    Zl, nullptr, gl, bl, FEAT, 0, (long)CCH*DD, HWD, HWD, DD, HWD };
        mma_gemm<2,1,256><<<dim3(DD/128, CCH/256, BATCH), blk, SMEM_256>>>(a);
    }
    // 3) norm Yv rows -> split E/O
    k_norm_v2l<<<BATCH*DD, blk>>>((const float4*)Yv,
        (uint32_t*)Eh, (uint32_t*)El, (uint32_t*)Oh, (uint32_t*)Ol);
    // 4) norm Zl rows -> split Zh/Zlo
    k_norm_rows<<<BATCH*CCH, 128>>>(Zl, (uint32_t*)Zh, (uint32_t*)Zlo);
    // 5) lat = E.Vlow^T + O.Vhigh^T  M=256 N=1024 K=1024x2 -> split bf16 out
    {
        GArgs a = { Eh, El, v2lh, v2ll, Oh, Ol, v2lh + (long)HWD*HWD, v2ll + (long)HWD*HWD,
                    lath, latl, nullptr, nullptr,
                    (long)DD*HWD, FEAT, (long)DD*HWD, HWD, HWD, HWD, HWD };
        mma_gemm<3,2,256><<<dim3(HWD/128, DD/256, BATCH), blk, SMEM_256>>>(a);
    }
    // 6) transpose lat -> latT
    k_transpose<<<dim3(32, 8, BATCH), blk>>>(
        (const uint32_t*)lath, (const uint32_t*)latl, (uint32_t*)latTh, (uint32_t*)latTl);
    // 7) latent row inverse norms
    k_latnorm<<<BATCH*DD, blk>>>((const uint32_t*)lath, (const uint32_t*)latl, invr);
    // 8) G = lat . lat^T  M=N=256 K=1024 (fp32 out)
    {
        GArgs a = { lath, latl, lath, latl, nullptr, nullptr, nullptr, nullptr,
                    G, nullptr, nullptr, nullptr,
                    (long)DD*HWD, (long)DD*HWD, (long)DD*DD, HWD, HWD, DD, HWD };
        mma_gemm<0,1,128><<<dim3(DD/128, DD/128, BATCH), blk, SMEM_128>>>(a);
    }
    // 9) aff = softmax(G * invr_d * invr_e) -> split bf16
    k_softmax<<<BATCH*DD, blk>>>(G, invr, (uint32_t*)Ghb, (uint32_t*)Glb);
    // 10) l2T = latT . aff^T  M=1024 N=256 K=256 -> split bf16
    {
        GArgs a = { latTh, latTl, Ghb, Glb, nullptr, nullptr, nullptr, nullptr,
                    l2Th, l2Tl, nullptr, nullptr,
                    (long)HWD*DD, (long)DD*DD, (long)HWD*DD, DD, DD, DD, DD };
        mma_gemm<3,1,128><<<dim3(DD/128, HWD/128, BATCH), blk, SMEM_128>>>(a);
    }
    // 11) out = Zl_adj . l2T^T  M=2048 N=1024 K=256 (fp32 out)
    {
        GArgs a = { Zh, Zlo, l2Th, l2Tl, nullptr, nullptr, nullptr, nullptr,
                    out, nullptr, nullptr, nullptr,
                    (long)CCH*DD, (long)HWD*DD, (long)CCH*HWD, DD, DD, HWD, DD };
        mma_gemm<0,1,256><<<dim3(HWD/128, CCH/256, BATCH), blk, SMEM_256>>>(a);
    }
}

// round 7
// speedup vs baseline: 2.2358x; 1.0000x over previous
#include <cuda_runtime.h>
#include <cuda_bf16.h>
#include <math.h>
#include <stdint.h>

#define BATCH 16
#define CCH   2048
#define HWD   1024
#define DD    256
#define BN_RS 0.9999950000374997f   // 1/sqrt(1 + 1e-5)

// ---------------- scratch (device globals; no allocation) ----------------
__device__ __align__(16) float d_Yv [BATCH * DD  * CCH];   // psi(v2l) fp32
__device__ __align__(16) float d_Zl [BATCH * CCH * DD ];   // psi(l2v)^T fp32
__device__ __align__(16) float d_G  [BATCH * DD  * DD ];   // gram fp32
__device__ float d_invr[BATCH * DD];

// bf16 hi/lo split operand storage
__device__ __align__(16) __nv_bfloat16 g_v2lh[BATCH*CCH*HWD], g_v2ll[BATCH*CCH*HWD];
__device__ __align__(16) __nv_bfloat16 g_l2vh[BATCH*CCH*HWD], g_l2vl[BATCH*CCH*HWD];
__device__ __align__(16) __nv_bfloat16 g_wvh[DD*HWD], g_wvl[DD*HWD];
__device__ __align__(16) __nv_bfloat16 g_wlh[DD*HWD], g_wll[DD*HWD];
__device__ __align__(16) __nv_bfloat16 g_Eh[BATCH*DD*HWD], g_El[BATCH*DD*HWD];
__device__ __align__(16) __nv_bfloat16 g_Oh[BATCH*DD*HWD], g_Ol[BATCH*DD*HWD];
__device__ __align__(16) __nv_bfloat16 g_Zh[BATCH*CCH*DD], g_Zlo[BATCH*CCH*DD];
__device__ __align__(16) __nv_bfloat16 g_lath[BATCH*DD*HWD], g_latl[BATCH*DD*HWD];
__device__ __align__(16) __nv_bfloat16 g_latTh[BATCH*HWD*DD], g_latTl[BATCH*HWD*DD];
__device__ __align__(16) __nv_bfloat16 g_Gh[BATCH*DD*DD], g_Gl[BATCH*DD*DD];
__device__ __align__(16) __nv_bfloat16 g_l2Th[BATCH*HWD*DD], g_l2Tl[BATCH*HWD*DD];

// ---------------- helpers ----------------
__device__ __forceinline__ uint32_t cvta_s(const void* p){
    return (uint32_t)__cvta_generic_to_shared(p);
}
__device__ __forceinline__ void cpa16(uint32_t d, const void* s){
    asm volatile("cp.async.cg.shared.global [%0], [%1], 16;" :: "r"(d), "l"(s));
}
#define CP_COMMIT() asm volatile("cp.async.commit_group;")
#define CP_WAIT2()  asm volatile("cp.async.wait_group 2;")

#define LDSM4(R, addr) \
    asm volatile("ldmatrix.sync.aligned.m8n8.x4.shared.b16 {%0,%1,%2,%3}, [%4];" \
        : "=r"((R)[0]), "=r"((R)[1]), "=r"((R)[2]), "=r"((R)[3]) : "r"(addr))

#define MMA16816(d, A, b0, b1) \
    asm volatile("mma.sync.aligned.m16n8k16.row.col.f32.bf16.bf16.f32 " \
        "{%0,%1,%2,%3}, {%4,%5,%6,%7}, {%8,%9}, {%0,%1,%2,%3};" \
        : "+f"((d)[0]), "+f"((d)[1]), "+f"((d)[2]), "+f"((d)[3]) \
        : "r"((A)[0]), "r"((A)[1]), "r"((A)[2]), "r"((A)[3]), "r"(b0), "r"(b1))

// split float4 -> packed bf16x2 hi (trunc) / lo (rn of exact residual)
__device__ __forceinline__ void split16(float4 v, uint2& hi, uint2& lo){
    uint32_t ux = __float_as_uint(v.x), uy = __float_as_uint(v.y);
    uint32_t uz = __float_as_uint(v.z), uw = __float_as_uint(v.w);
    hi.x = __byte_perm(ux, uy, 0x7632);
    hi.y = __byte_perm(uz, uw, 0x7632);
    float lx = v.x - __uint_as_float(ux & 0xFFFF0000u);
    float ly = v.y - __uint_as_float(uy & 0xFFFF0000u);
    float lz = v.z - __uint_as_float(uz & 0xFFFF0000u);
    float lw = v.w - __uint_as_float(uw & 0xFFFF0000u);
    __nv_bfloat162 l01 = __floats2bfloat162_rn(lx, ly);
    __nv_bfloat162 l23 = __floats2bfloat162_rn(lz, lw);
    lo.x = *(uint32_t*)&l01;
    lo.y = *(uint32_t*)&l23;
}
__device__ __forceinline__ uint32_t pack_hi(float x, float y){
    return __byte_perm(__float_as_uint(x), __float_as_uint(y), 0x7632);
}
__device__ __forceinline__ uint32_t pack_lo(float x, float y){
    float lx = x - __uint_as_float(__float_as_uint(x) & 0xFFFF0000u);
    float ly = y - __uint_as_float(__float_as_uint(y) & 0xFFFF0000u);
    __nv_bfloat162 p = __floats2bfloat162_rn(lx, ly);
    return *(uint32_t*)&p;
}

// ---------------- bf16 hi/lo NT GEMM, cp.async pipelined -------------------
// D[m,n] = sum_p sum_k A_p[m,k]*B_p[n,k], 3 bf16 passes (hh + hl + lh)
struct GArgs {
    const __nv_bfloat16 *A0h, *A0l, *B0h, *B0l;
    const __nv_bfloat16 *A1h, *A1l, *B1h, *B1l;
    void *C, *C2;                   // EPI 0/1/2: C=float*; EPI 3: C=hi bf16*, C2=lo bf16*
    const float *gs, *bs;
    long sA, sB, sC;
    int lda, ldb, ldc, K;
};

// Tile: BM x 128, K-chunk 32. Stage: Ah(BM*64) Al(BM*64) Bh(8K) Bl(8K).
// Row = 64B (32 bf16), 4x16B chunks, swizzled quarter q = ch ^ ((row>>1)&3).
template<int EPI, int NP, int BM>
__global__ void __launch_bounds__(256, 1) mma_gemm(GArgs a)
{
    constexpr int WNW  = (BM == 128) ? 32 : 64;  // warp N width
    constexpr int NI   = WNW / 8;                // 4 or 8 n8-blocks per warp
    constexpr int NB   = WNW / 16;               // 2 or 4 ldmatrix B blocks
    constexpr int GSUBA = BM * 64;               // bytes per A subtile
    constexpr int GS    = 2 * GSUBA + 16384;     // stage bytes
    constexpr int BOFF  = 2 * GSUBA;             // Bh offset in stage

    extern __shared__ __align__(128) char smem[];
    const int tid = threadIdx.x, w = tid >> 5, lane = tid & 31;
    const int bn0 = blockIdx.x << 7, bm0 = blockIdx.y * BM, b = blockIdx.z;
    const int KS = a.K >> 5;
    const int NS = KS * NP;
    const uint32_t sbase = cvta_s(smem);
    const int wm = (BM == 128) ? (w >> 2) : (w >> 1);
    const int wn = (BM == 128) ? (w & 3)  : (w & 1);

    // cp.async mapping
    const int r0 = tid >> 2, ch = tid & 3;
    const uint32_t q16 = (uint32_t)((ch ^ ((r0 >> 1) & 3)) * 16);

    auto issue = [&](int s){
        int p = (NP == 2 && s >= KS) ? 1 : 0;
        long k0 = (long)(s - p * KS) * 32;
        const __nv_bfloat16* Ah = (p ? a.A1h : a.A0h) + (long)b * a.sA + (long)bm0 * a.lda + k0;
        const __nv_bfloat16* Al = (p ? a.A1l : a.A0l) + (long)b * a.sA + (long)bm0 * a.lda + k0;
        const __nv_bfloat16* Bh = (p ? a.B1h : a.B0h) + (long)b * a.sB + (long)bn0 * a.ldb + k0;
        const __nv_bfloat16* Bl = (p ? a.B1l : a.B0l) + (long)b * a.sB + (long)bn0 * a.ldb + k0;
        uint32_t dst0 = sbase + (uint32_t)(s & 3) * GS + (uint32_t)r0 * 64u + q16;
        const __nv_bfloat16* ap = Ah + (long)r0 * a.lda + ch * 8;
        const __nv_bfloat16* lp = Al + (long)r0 * a.lda + ch * 8;
        #pragma unroll
        for (int jj = 0; jj < BM / 64; jj++){
            cpa16(dst0 + jj * 4096,         ap + (long)jj * 64 * a.lda);
            cpa16(dst0 + GSUBA + jj * 4096, lp + (long)jj * 64 * a.lda);
        }
        const __nv_bfloat16* bp = Bh + (long)r0 * a.ldb + ch * 8;
        const __nv_bfloat16* blp = Bl + (long)r0 * a.ldb + ch * 8;
        #pragma unroll
        for (int jj = 0; jj < 2; jj++){
            cpa16(dst0 + BOFF + jj * 4096,        bp + (long)jj * 64 * a.ldb);
            cpa16(dst0 + BOFF + 8192 + jj * 4096, blp + (long)jj * 64 * a.ldb);
        }
    };

    float acc[4][NI][4];
    #pragma unroll
    for (int i = 0; i < 4; i++)
        #pragma unroll
        for (int j = 0; j < NI; j++)
            #pragma unroll
            for (int t = 0; t < 4; t++) acc[i][j][t] = 0.0f;

    // ldmatrix addressing
    const int aRow = wm * 64 + (lane & 15);
    const uint32_t lqA = (uint32_t)(((lane & 15) >> 1) & 3);
    const uint32_t aC0 = (uint32_t)(lane >> 4);
    const int bRow = wn * WNW + (lane & 7) + ((lane >> 4) & 1) * 8;
    const uint32_t lqB = (uint32_t)(((lane & 7) >> 1) & 3);
    const uint32_t bC0 = (uint32_t)((lane >> 3) & 1);

    // prologue: 3 stages in flight
    #pragma unroll
    for (int s = 0; s < 3; s++){ if (s < NS) issue(s); CP_COMMIT(); }

    for (int i = 0; i < NS; i++){
        CP_WAIT2();
        __syncthreads();
        if (i + 3 < NS) issue(i + 3);    // overlap DMA with the MMA block below
        CP_COMMIT();

        const uint32_t stb = sbase + (uint32_t)(i & 3) * GS;
        #pragma unroll
        for (int ks = 0; ks < 2; ks++){
            uint32_t Afh[4][4], Afl[4][4], Bfh[NB][4], Bfl[NB][4];
            const uint32_t qa = ((aC0 + 2 * ks) ^ lqA) * 16u;
            const uint32_t qb = ((bC0 + 2 * ks) ^ lqB) * 16u;
            #pragma unroll
            for (int mi = 0; mi < 4; mi++){
                uint32_t ad = stb + (uint32_t)(aRow + mi * 16) * 64u + qa;
                LDSM4(Afh[mi], ad);
                LDSM4(Afl[mi], ad + GSUBA);
            }
            #pragma unroll
            for (int nb = 0; nb < NB; nb++){
                uint32_t bd = stb + BOFF + (uint32_t)(bRow + nb * 16) * 64u + qb;
                LDSM4(Bfh[nb], bd);
                LDSM4(Bfl[nb], bd + 8192);
            }
            // pass 1: Ah*Bh
            #pragma unroll
            for (int mi = 0; mi < 4; mi++)
                #pragma unroll
                for (int ni = 0; ni < NI; ni++){
                    int nb = ni >> 1, h = (ni & 1) * 2;
                    MMA16816(acc[mi][ni], Afh[mi], Bfh[nb][h], Bfh[nb][h + 1]);
                }
            // pass 2: Ah*Bl
            #pragma unroll
            for (int mi = 0; mi < 4; mi++)
                #pragma unroll
                for (int ni = 0; ni < NI; ni++){
                    int nb = ni >> 1, h = (ni & 1) * 2;
                    MMA16816(acc[mi][ni], Afh[mi], Bfl[nb][h], Bfl[nb][h + 1]);
                }
            // pass 3: Al*Bh
            #pragma unroll
            for (int mi = 0; mi < 4; mi++)
                #pragma unroll
                for (int ni = 0; ni < NI; ni++){
                    int nb = ni >> 1, h = (ni & 1) * 2;
                    MMA16816(acc[mi][ni], Afl[mi], Bfh[nb][h], Bfh[nb][h + 1]);
                }
        }
    }

    // ---- epilogue
    const int r1 = lane >> 2, cq = (lane & 3) * 2;
    if (EPI == 3){
        __nv_bfloat16* Ch = (__nv_bfloat16*)a.C;
        __nv_bfloat16* Cl = (__nv_bfloat16*)a.C2;
        const long cb = (long)b * a.sC;
        #pragma unroll
        for (int mi = 0; mi < 4; mi++){
            int m0 = bm0 + wm * 64 + mi * 16 + r1;
            #pragma unroll
            for (int ni = 0; ni < NI; ni++){
                int n = bn0 + wn * WNW + ni * 8 + cq;
                float v0 = acc[mi][ni][0], v1 = acc[mi][ni][1];
                float v2 = acc[mi][ni][2], v3 = acc[mi][ni][3];
                *(uint32_t*)(Ch + cb + (long)m0 * a.ldc + n)       = pack_hi(v0, v1);
                *(uint32_t*)(Cl + cb + (long)m0 * a.ldc + n)       = pack_lo(v0, v1);
                *(uint32_t*)(Ch + cb + (long)(m0 + 8) * a.ldc + n) = pack_hi(v2, v3);
                *(uint32_t*)(Cl + cb + (long)(m0 + 8) * a.ldc + n) = pack_lo(v2, v3);
            }
        }
    } else {
        float* Cb = (float*)a.C + (long)b * a.sC;
        #pragma unroll
        for (int mi = 0; mi < 4; mi++){
            int m0 = bm0 + wm * 64 + mi * 16 + r1;
            float s0 = 0.f, b0_ = 0.f, s1 = 0.f, b1_ = 0.f;
            if (EPI == 1){
                s0 = a.gs[m0] * BN_RS;     b0_ = a.bs[m0];
                s1 = a.gs[m0 + 8] * BN_RS; b1_ = a.bs[m0 + 8];
            }
            #pragma unroll
            for (int ni = 0; ni < NI; ni++){
                int n = bn0 + wn * WNW + ni * 8 + cq;
                float v0 = acc[mi][ni][0], v1 = acc[mi][ni][1];
                float v2 = acc[mi][ni][2], v3 = acc[mi][ni][3];
                if (EPI == 1){
                    v0 = fmaxf(fmaf(v0, s0, b0_), 0.f); v1 = fmaxf(fmaf(v1, s0, b0_), 0.f);
                    v2 = fmaxf(fmaf(v2, s1, b1_), 0.f); v3 = fmaxf(fmaf(v3, s1, b1_), 0.f);
                } else if (EPI == 2){
                    float gs0 = a.gs[n] * BN_RS, bb0 = a.bs[n];
                    float gs1 = a.gs[n + 1] * BN_RS, bb1 = a.bs[n + 1];
                    v0 = fmaxf(fmaf(v0, gs0, bb0), 0.f); v1 = fmaxf(fmaf(v1, gs1, bb1), 0.f);
                    v2 = fmaxf(fmaf(v2, gs0, bb0), 0.f); v3 = fmaxf(fmaf(v3, gs1, bb1), 0.f);
                }
                *(float2*)(Cb + (long)m0 * a.ldc + n)       = make_float2(v0, v1);
                *(float2*)(Cb + (long)(m0 + 8) * a.ldc + n) = make_float2(v2, v3);
            }
        }
    }
}

#define SMEM_128 (4 * (2 * 128 * 64 + 16384))
#define SMEM_256 (4 * (2 * 256 * 64 + 16384))

// ---------------- reductions ----------------
__device__ __forceinline__ float warpSum(float v){
    #pragma unroll
    for (int o = 16; o; o >>= 1) v += __shfl_xor_sync(0xffffffffu, v, o);
    return v;
}
__device__ __forceinline__ float warpMax(float v){
    #pragma unroll
    for (int o = 16; o; o >>= 1) v = fmaxf(v, __shfl_xor_sync(0xffffffffu, v, o));
    return v;
}
__device__ __forceinline__ float blockSum(float v){
    __shared__ float sh[32];
    int w = threadIdx.x >> 5, l = threadIdx.x & 31;
    v = warpSum(v);
    if (l == 0) sh[w] = v;
    __syncthreads();
    int nw = blockDim.x >> 5;
    if (w == 0){ float x = (l < nw) ? sh[l] : 0.0f; x = warpSum(x); if (l == 0) sh[0] = x; }
    __syncthreads();
    float r = sh[0];
    __syncthreads();
    return r;
}
__device__ __forceinline__ float blockMax(float v){
    __shared__ float sh[32];
    int w = threadIdx.x >> 5, l = threadIdx.x & 31;
    v = warpMax(v);
    if (l == 0) sh[w] = v;
    __syncthreads();
    int nw = blockDim.x >> 5;
    if (w == 0){ float x = (l < nw) ? sh[l] : -INFINITY; x = warpMax(x); if (l == 0) sh[0] = x; }
    __syncthreads();
    float r = sh[0];
    __syncthreads();
    return r;
}

// ---------------- elementwise kernels ----------------
__global__ void __launch_bounds__(256)
k_split(const float4* __restrict__ in, uint2* __restrict__ hi, uint2* __restrict__ lo, int n4)
{
    int i = blockIdx.x * blockDim.x + threadIdx.x;
    int stride = gridDim.x * blockDim.x;
    for (; i < n4; i += stride){
        float4 v = in[i];
        uint2 h, l;
        split16(v, h, l);
        hi[i] = h;
        lo[i] = l;
    }
}

// normalize Yv rows over C=2048, deinterleave even/odd channels, write split bf16
__global__ void __launch_bounds__(256)
k_norm_v2l(const float4* __restrict__ Y,
           uint32_t* __restrict__ Eh, uint32_t* __restrict__ El,
           uint32_t* __restrict__ Oh, uint32_t* __restrict__ Ol)
{
    long row = blockIdx.x;
    const float4* y = Y + row * 512;
    int t = threadIdx.x;
    float4 v0 = y[t], v1 = y[t + 256];
    float s = v0.x*v0.x + v0.y*v0.y + v0.z*v0.z + v0.w*v0.w
            + v1.x*v1.x + v1.y*v1.y + v1.z*v1.z + v1.w*v1.w;
    s = blockSum(s);
    float inv = 1.0f / fmaxf(sqrtf(s), 1e-12f);
    long eb = row * 512;
    Eh[eb + t] = pack_hi(v0.x * inv, v0.z * inv);
    El[eb + t] = pack_lo(v0.x * inv, v0.z * inv);
    Oh[eb + t] = pack_hi(v0.y * inv, v0.w * inv);
    Ol[eb + t] = pack_lo(v0.y * inv, v0.w * inv);
    Eh[eb + t + 256] = pack_hi(v1.x * inv, v1.z * inv);
    El[eb + t + 256] = pack_lo(v1.x * inv, v1.z * inv);
    Oh[eb + t + 256] = pack_hi(v1.y * inv, v1.w * inv);
    Ol[eb + t + 256] = pack_lo(v1.y * inv, v1.w * inv);
}

// normalize Zl rows over D=256, write split bf16
__global__ void __launch_bounds__(128)
k_norm_rows(const float* __restrict__ Z, uint32_t* __restrict__ Zh, uint32_t* __restrict__ Zl)
{
    long row = blockIdx.x;
    const float2* z = (const float2*)(Z + row * 256);
    int t = threadIdx.x;
    float2 v = z[t];
    float s = blockSum(v.x * v.x + v.y * v.y);
    float inv = 1.0f / fmaxf(sqrtf(s), 1e-12f);
    Zh[row * 128 + t] = pack_hi(v.x * inv, v.y * inv);
    Zl[row * 128 + t] = pack_lo(v.x * inv, v.y * inv);
}

// transpose lat_hi/lo [b,256,1024] -> latT_hi/lo [b,1024,256]
__global__ void __launch_bounds__(256)
k_transpose(const uint32_t* __restrict__ sH, const uint32_t* __restrict__ sL,
            uint32_t* __restrict__ dH, uint32_t* __restrict__ dL)
{
    __shared__ unsigned short tile[32][34];
    const int b = blockIdx.z, h0 = blockIdx.x * 32, d0 = blockIdx.y * 32;
    const int t = threadIdx.x;
    const uint32_t* srcs[2] = {sH, sL};
    uint32_t* dsts[2] = {dH, dL};
    #pragma unroll
    for (int m = 0; m < 2; m++){
        #pragma unroll
        for (int i = 0; i < 2; i++){
            int s = t + i * 256;
            int d = s >> 4, hu = s & 15;
            uint32_t v = srcs[m][(long)(b * 256 + d0 + d) * 512 + (h0 >> 1) + hu];
            tile[d][2 * hu]     = (unsigned short)(v & 0xFFFFu);
            tile[d][2 * hu + 1] = (unsigned short)(v >> 16);
        }
        __syncthreads();
        #pragma unroll
        for (int i = 0; i < 2; i++){
            int s = t + i * 256;
            int h = s >> 4, du = s & 15;
            uint32_t v = (uint32_t)tile[2 * du][h] | ((uint32_t)tile[2 * du + 1][h] << 16);
            dsts[m][(long)(b * 1024 + h0 + h) * 128 + (d0 >> 1) + du] = v;
        }
        __syncthreads();
    }
}

// latent row inverse norms from hi/lo
__global__ void __launch_bounds__(256)
k_latnorm(const uint32_t* __restrict__ H, const uint32_t* __restrict__ L, float* __restrict__ R)
{
    long row = blockIdx.x;
    long base = row * 512;
    int t = threadIdx.x;
    float s = 0.0f;
    #pragma unroll
    for (int i = 0; i < 2; i++){
        long idx = base + t + i * 256;
        uint32_t uh = H[idx], ul = L[idx];
        float2 fh = __bfloat1622float2(*(__nv_bfloat162*)&uh);
        float2 fl = __bfloat1622float2(*(__nv_bfloat162*)&ul);
        float v0 = fh.x + fl.x, v1 = fh.y + fl.y;
        s += v0 * v0 + v1 * v1;
    }
    s = blockSum(s);
    if (t == 0) R[row] = 1.0f / fmaxf(sqrtf(s), 1e-12f);
}

// softmax over scaled gram rows; write split bf16
__global__ void __launch_bounds__(256)
k_softmax(const float* __restrict__ G, const float* __restrict__ R,
          uint32_t* __restrict__ Gh, uint32_t* __restrict__ Gl)
{
    long row = blockIdx.x;
    long bb = row >> 8;
    int t = threadIdx.x;
    float ri = R[row];
    float re = R[(bb << 8) + t];
    float x = G[row * 256 + t] * ri * re;
    float mx = blockMax(x);
    float p = expf(x - mx);
    float sm = blockSum(p);
    float g = p / sm;
    float gn = __shfl_down_sync(0xffffffffu, g, 1);
    if ((t & 1) == 0){
        Gh[row * 128 + (t >> 1)] = pack_hi(g, gn);
        Gl[row * 128 + (t >> 1)] = pack_lo(g, gn);
    }
}

// ---------------- launch ----------------
extern "C" void kernel_launch(void* const* d_in, const int* in_sizes, int n_in,
                              void* d_out, int out_size)
{
    const float* v2l = (const float*)d_in[0];
    const float* l2v = (const float*)d_in[1];
    const float* wv  = (const float*)d_in[2];
    const float* gv  = (const float*)d_in[3];
    const float* bv  = (const float*)d_in[4];
    const float* wl  = (const float*)d_in[5];
    const float* gl  = (const float*)d_in[6];
    const float* bl  = (const float*)d_in[7];
    float* out = (float*)d_out;

    float *Yv, *Zl, *G, *invr;
    __nv_bfloat16 *v2lh, *v2ll, *l2vh, *l2vl, *wvh, *wvl, *wlh, *wll;
    __nv_bfloat16 *Eh, *El, *Oh, *Ol, *Zh, *Zlo, *lath, *latl, *latTh, *latTl;
    __nv_bfloat16 *Ghb, *Glb, *l2Th, *l2Tl;
    cudaGetSymbolAddress((void**)&Yv, d_Yv);
    cudaGetSymbolAddress((void**)&Zl, d_Zl);
    cudaGetSymbolAddress((void**)&G, d_G);
    cudaGetSymbolAddress((void**)&invr, d_invr);
    cudaGetSymbolAddress((void**)&v2lh, g_v2lh); cudaGetSymbolAddress((void**)&v2ll, g_v2ll);
    cudaGetSymbolAddress((void**)&l2vh, g_l2vh); cudaGetSymbolAddress((void**)&l2vl, g_l2vl);
    cudaGetSymbolAddress((void**)&wvh, g_wvh);   cudaGetSymbolAddress((void**)&wvl, g_wvl);
    cudaGetSymbolAddress((void**)&wlh, g_wlh);   cudaGetSymbolAddress((void**)&wll, g_wll);
    cudaGetSymbolAddress((void**)&Eh, g_Eh);     cudaGetSymbolAddress((void**)&El, g_El);
    cudaGetSymbolAddress((void**)&Oh, g_Oh);     cudaGetSymbolAddress((void**)&Ol, g_Ol);
    cudaGetSymbolAddress((void**)&Zh, g_Zh);     cudaGetSymbolAddress((void**)&Zlo, g_Zlo);
    cudaGetSymbolAddress((void**)&lath, g_lath); cudaGetSymbolAddress((void**)&latl, g_latl);
    cudaGetSymbolAddress((void**)&latTh, g_latTh); cudaGetSymbolAddress((void**)&latTl, g_latTl);
    cudaGetSymbolAddress((void**)&Ghb, g_Gh);    cudaGetSymbolAddress((void**)&Glb, g_Gl);
    cudaGetSymbolAddress((void**)&l2Th, g_l2Th); cudaGetSymbolAddress((void**)&l2Tl, g_l2Tl);

    cudaFuncSetAttribute(mma_gemm<1,1,256>, cudaFuncAttributeMaxDynamicSharedMemorySize, SMEM_256);
    cudaFuncSetAttribute(mma_gemm<2,1,256>, cudaFuncAttributeMaxDynamicSharedMemorySize, SMEM_256);
    cudaFuncSetAttribute(mma_gemm<3,2,256>, cudaFuncAttributeMaxDynamicSharedMemorySize, SMEM_256);
    cudaFuncSetAttribute(mma_gemm<0,1,256>, cudaFuncAttributeMaxDynamicSharedMemorySize, SMEM_256);
    cudaFuncSetAttribute(mma_gemm<0,1,128>, cudaFuncAttributeMaxDynamicSharedMemorySize, SMEM_128);
    cudaFuncSetAttribute(mma_gemm<3,1,128>, cudaFuncAttributeMaxDynamicSharedMemorySize, SMEM_128);

    const long FEAT = (long)CCH * HWD;
    dim3 blk(256);

    // 0) splits of raw inputs + weights
    k_split<<<8192, blk>>>((const float4*)v2l, (uint2*)v2lh, (uint2*)v2ll, (int)(BATCH*FEAT/4));
    k_split<<<8192, blk>>>((const float4*)l2v, (uint2*)l2vh, (uint2*)l2vl, (int)(BATCH*FEAT/4));
    k_split<<<256, blk>>>((const float4*)wv, (uint2*)wvh, (uint2*)wvl, DD*HWD/4);
    k_split<<<256, blk>>>((const float4*)wl, (uint2*)wlh, (uint2*)wll, DD*HWD/4);

    // 1) Yv = relu(bn(Wv . V^T))  M=256 N=2048 K=1024
    {
        GArgs a = { wvh, wvl, v2lh, v2ll, nullptr, nullptr, nullptr, nullptr,
                    Yv, nullptr, gv, bv, 0, FEAT, (long)DD*CCH, HWD, HWD, CCH, HWD };
        mma_gemm<1,1,256><<<dim3(CCH/128, DD/256, BATCH), blk, SMEM_256>>>(a);
    }
    // 2) Zl = relu(bn(Xl . Wl^T)) M=2048 N=256 K=1024
    {
        GArgs a = { l2vh, l2vl, wlh, wll, nullptr, nullptr, nullptr, nullptr,
                    Zl, nullptr, gl, bl, FEAT, 0, (long)CCH*DD, HWD, HWD, DD, HWD };
        mma_gemm<2,1,256><<<dim3(DD/128, CCH/256, BATCH), blk, SMEM_256>>>(a);
    }
    // 3) norm Yv rows -> split E/O
    k_norm_v2l<<<BATCH*DD, blk>>>((const float4*)Yv,
        (uint32_t*)Eh, (uint32_t*)El, (uint32_t*)Oh, (uint32_t*)Ol);
    // 4) norm Zl rows -> split Zh/Zlo
    k_norm_rows<<<BATCH*CCH, 128>>>(Zl, (uint32_t*)Zh, (uint32_t*)Zlo);
    // 5) lat = E.Vlow^T + O.Vhigh^T  M=256 N=1024 K=1024x2 -> split bf16 out
    {
        GArgs a = { Eh, El, v2lh, v2ll, Oh, Ol, v2lh + (long)HWD*HWD, v2ll + (long)HWD*HWD,
                    lath, latl, nullptr, nullptr,
                    (long)DD*HWD, FEAT, (long)DD*HWD, HWD, HWD, HWD, HWD };
        mma_gemm<3,2,256><<<dim3(HWD/128, DD/256, BATCH), blk, SMEM_256>>>(a);
    }
    // 6) transpose lat -> latT
    k_transpose<<<dim3(32, 8, BATCH), blk>>>(
        (const uint32_t*)lath, (const uint32_t*)latl, (uint32_t*)latTh, (uint32_t*)latTl);
    // 7) latent row inverse norms
    k_latnorm<<<BATCH*DD, blk>>>((const uint32_t*)lath, (const uint32_t*)latl, invr);
    // 8) G = lat . lat^T  M=N=256 K=1024 (fp32 out)
    {
        GArgs a = { lath, latl, lath, latl, nullptr, nullptr, nullptr, nullptr,
                    G, nullptr, nullptr, nullptr,
                    (long)DD*HWD, (long)DD*HWD, (long)DD*DD, HWD, HWD, DD, HWD };
        mma_gemm<0,1,128><<<dim3(DD/128, DD/128, BATCH), blk, SMEM_128>>>(a);
    }
    // 9) aff = softmax(G * invr_d * invr_e) -> split bf16
    k_softmax<<<BATCH*DD, blk>>>(G, invr, (uint32_t*)Ghb, (uint32_t*)Glb);
    // 10) l2T = latT . aff^T  M=1024 N=256 K=256 -> split bf16
    {
        GArgs a = { latTh, latTl, Ghb, Glb, nullptr, nullptr, nullptr, nullptr,
                    l2Th, l2Tl, nullptr, nullptr,
                    (long)HWD*DD, (long)DD*DD, (long)HWD*DD, DD, DD, DD, DD };
        mma_gemm<3,1,128><<<dim3(DD/128, HWD/128, BATCH), blk, SMEM_128>>>(a);
    }
    // 11) out = Zl_adj . l2T^T  M=2048 N=1024 K=256 (fp32 out)
    {
        GArgs a = { Zh, Zlo, l2Th, l2Tl, nullptr, nullptr, nullptr, nullptr,
                    out, nullptr, nullptr, nullptr,
                    (long)CCH*DD, (long)HWD*DD, (long)CCH*HWD, DD, DD, HWD, DD };
        mma_gemm<0,1,256><<<dim3(HWD/128, CCH/256, BATCH), blk, SMEM_256>>>(a);
    }
}